// round 11
// baseline (speedup 1.0000x reference)
#include <cuda_runtime.h>
#include <cstdint>

#define NUSERS 100000
#define NITEMS 50000
#define EMBED 64
#define RREL 3
#define NNZ_E 1000000
#define IG_NNZ_E 500000
#define BB 512
#define KK 100
#define EPSF 1e-8f
#define SCORE2_SCALE (0.5f/3.0f)
#define L2C 1e-4f

#define IE (NITEMS*EMBED)
#define UBW 3200
#define IBW 1600

#define NB_IG 7813                 // ceil(500000/4*16 / 256) per relation
#define NB_TR 15625                // 1000000/4*16 / 256
#define NB_MM 512
#define NB_RH 128
#define NB_MID (NB_MM + RREL*NB_RH)

// ---------------- device scratch (static, allocation-free) ----------------
__device__ __align__(16) float g_item_agg[RREL*IE];
__device__ __align__(16) float g_item_feat[IE];
__device__ __align__(16) float g_item_featW[IE];
__device__ __align__(16) float g_ig_deg[RREL*NITEMS];
__device__ __align__(16) int   g_map[NUSERS];
__device__ __align__(16) unsigned g_ubit[UBW];
__device__ __align__(16) unsigned g_ibit[IBW];
__device__ __align__(16) unsigned g_nbit[IBW];
__device__ __align__(16) float g_udeg[RREL*BB];
__device__ __align__(16) float g_uacc[RREL*BB*128];
__device__ __align__(16) float g_proj[RREL*BB*128];
__device__ __align__(16) float g_u2[BB*EMBED];
__device__ __align__(16) int2  g_crel[RREL*NNZ_E];
__device__ int g_cnt_rel[RREL];
__device__ double g_l2i;

__device__ __forceinline__ void red_add_v4(float* addr, float4 v) {
    asm volatile("red.global.add.v4.f32 [%0], {%1,%2,%3,%4};"
                 :: "l"(addr), "f"(v.x), "f"(v.y), "f"(v.z), "f"(v.w) : "memory");
}

// ---------------- zero: small control structures ----------------
__global__ void k_zero_small() {
    int idx = blockIdx.x * blockDim.x + threadIdx.x;
    float4 z4 = make_float4(0.f,0.f,0.f,0.f);
    if (idx < RREL*BB*128/4)   reinterpret_cast<float4*>(g_uacc)[idx] = z4;
    if (idx < RREL*BB)         g_udeg[idx] = 0.f;
    if (idx < NUSERS/4)        reinterpret_cast<int4*>(g_map)[idx] = make_int4(-1,-1,-1,-1);
    if (idx < UBW)             g_ubit[idx] = 0u;
    if (idx < IBW)             { g_ibit[idx] = 0u; g_nbit[idx] = 0u; }
    if (idx < RREL)            g_cnt_rel[idx] = 0;
    if (idx == 0)              g_l2i = 0.0;
}

// ---------------- zero: big embedding planes ----------------
__global__ void k_zero_big() {
    int idx = blockIdx.x * blockDim.x + threadIdx.x;   // RREL*IE/4 = 2.4M
    float4 z4 = make_float4(0.f,0.f,0.f,0.f);
    if (idx < RREL*IE/4)       reinterpret_cast<float4*>(g_item_agg)[idx] = z4;
    if (idx < IE/4)            reinterpret_cast<float4*>(g_item_feat)[idx] = z4;
    if (idx < RREL*NITEMS/4)   reinterpret_cast<float4*>(g_ig_deg)[idx] = z4;
}

// ---------------- build maps / bitmaps ----------------
__global__ void k_map(const int* __restrict__ user, const int* __restrict__ item) {
    int idx = blockIdx.x * blockDim.x + threadIdx.x;
    if (idx < BB) {
        int uid = user[idx];
        g_map[uid] = idx;
        atomicOr(&g_ubit[uid >> 5], 1u << (uid & 31));
    }
    if (idx < BB*KK) {
        int it = item[idx];
        atomicOr(&g_ibit[it >> 5], 1u << (it & 31));
        atomicOr(&g_nbit[it >> 5], 1u << (it & 31));
    }
}

// ---------------- prescan rel edges: warp-aggregated compaction ----------------
__global__ void k_prescan_rel(const int* __restrict__ rows_all, const int* __restrict__ cols_all) {
    int r = blockIdx.y;
    const int* rows = rows_all + (size_t)r*NNZ_E;
    const int* cols = cols_all + (size_t)r*NNZ_E;
    int g = blockIdx.x * blockDim.x + threadIdx.x;
    int lane = threadIdx.x & 31;
    bool inrange = (g < NNZ_E/4);
    int e0 = g * 4;
    int4 rr = inrange ? *reinterpret_cast<const int4*>(rows + e0) : make_int4(0,0,0,0);
    #pragma unroll
    for (int q = 0; q < 4; q++) {
        int row = (q==0)?rr.x:(q==1)?rr.y:(q==2)?rr.z:rr.w;
        bool pass = false;
        if (inrange) {
            unsigned w = __ldg(&g_ubit[row >> 5]);
            pass = (w >> (row & 31)) & 1u;
        }
        unsigned m = __ballot_sync(0xffffffffu, pass);
        if (m == 0) continue;
        int cnt = __popc(m);
        int leader = __ffs(m) - 1;
        int base = 0;
        if (lane == leader) base = atomicAdd(&g_cnt_rel[r], cnt);
        base = __shfl_sync(0xffffffffu, base, leader);
        if (pass) {
            int rank = __popc(m & ((1u << lane) - 1u));
            int slot = g_map[row];
            int col = __ldg(&cols[e0 + q]);
            g_crel[(size_t)r*NNZ_E + base + rank] = make_int2(slot, col);
            atomicAdd(&g_udeg[r*BB + slot], 1.0f);
            atomicOr(&g_nbit[col >> 5], 1u << (col & 31));
        }
    }
}

// ---------------- train scatter (only needs ibit + zeroed item_feat) ----------
__global__ void k_scatter_tr(const int* __restrict__ tr_rows, const int* __restrict__ tr_cols,
                             const float* __restrict__ user_emb) {
    int t = blockIdx.x * 256 + threadIdx.x;
    int g = t >> 4;
    if (g >= NNZ_E/4) return;
    int p = t & 15;
    int e0 = g * 4;
    int4 cc = *reinterpret_cast<const int4*>(tr_cols + e0);
    int4 rr = *reinterpret_cast<const int4*>(tr_rows + e0);
    const float4* E = reinterpret_cast<const float4*>(user_emb);
    bool b0 = (__ldg(&g_ibit[cc.x >> 5]) >> (cc.x & 31)) & 1u;
    bool b1 = (__ldg(&g_ibit[cc.y >> 5]) >> (cc.y & 31)) & 1u;
    bool b2 = (__ldg(&g_ibit[cc.z >> 5]) >> (cc.z & 31)) & 1u;
    bool b3 = (__ldg(&g_ibit[cc.w >> 5]) >> (cc.w & 31)) & 1u;
    if (b0) { float4 x = E[(size_t)rr.x*16 + p]; red_add_v4(g_item_feat + (size_t)cc.x*64 + p*4, x); }
    if (b1) { float4 x = E[(size_t)rr.y*16 + p]; red_add_v4(g_item_feat + (size_t)cc.y*64 + p*4, x); }
    if (b2) { float4 x = E[(size_t)rr.z*16 + p]; red_add_v4(g_item_feat + (size_t)cc.z*64 + p*4, x); }
    if (b3) { float4 x = E[(size_t)rr.w*16 + p]; red_add_v4(g_item_feat + (size_t)cc.w*64 + p*4, x); }
}

// ---------------- ig scatter, 3 relations flattened (needs nbit from prescan) --
__global__ void k_scatter_ig(const int* __restrict__ ig_rows_all, const int* __restrict__ ig_cols_all,
                             const float* __restrict__ ig_vals_all, const float* __restrict__ item_emb) {
    int bx = blockIdx.x;
    int r = bx / NB_IG;
    int bxx = bx - r*NB_IG;
    const int*   rows = ig_rows_all + (size_t)r*IG_NNZ_E;
    const int*   cols = ig_cols_all + (size_t)r*IG_NNZ_E;
    const float* vals = ig_vals_all + (size_t)r*IG_NNZ_E;
    float* agg = g_item_agg + (size_t)r*IE;
    float* deg = g_ig_deg + (size_t)r*NITEMS;
    int t = bxx * 256 + threadIdx.x;
    int g = t >> 4;
    if (g >= IG_NNZ_E/4) return;
    int p = t & 15;
    int e0 = g * 4;
    int4  rr = *reinterpret_cast<const int4*>(rows + e0);
    int4   c = *reinterpret_cast<const int4*>(cols + e0);
    float4 v = *reinterpret_cast<const float4*>(vals + e0);
    const float4* E = reinterpret_cast<const float4*>(item_emb);
    bool n0 = (__ldg(&g_nbit[rr.x >> 5]) >> (rr.x & 31)) & 1u;
    bool n1 = (__ldg(&g_nbit[rr.y >> 5]) >> (rr.y & 31)) & 1u;
    bool n2 = (__ldg(&g_nbit[rr.z >> 5]) >> (rr.z & 31)) & 1u;
    bool n3 = (__ldg(&g_nbit[rr.w >> 5]) >> (rr.w & 31)) & 1u;
    if (n0) { float4 x = E[(size_t)c.x*16 + p]; x.x*=v.x; x.y*=v.x; x.z*=v.x; x.w*=v.x;
              red_add_v4(agg + (size_t)rr.x*64 + p*4, x); }
    if (n1) { float4 x = E[(size_t)c.y*16 + p]; x.x*=v.y; x.y*=v.y; x.z*=v.y; x.w*=v.y;
              red_add_v4(agg + (size_t)rr.y*64 + p*4, x); }
    if (n2) { float4 x = E[(size_t)c.z*16 + p]; x.x*=v.z; x.y*=v.z; x.z*=v.z; x.w*=v.z;
              red_add_v4(agg + (size_t)rr.z*64 + p*4, x); }
    if (n3) { float4 x = E[(size_t)c.w*16 + p]; x.x*=v.w; x.y*=v.w; x.z*=v.w; x.w*=v.w;
              red_add_v4(agg + (size_t)rr.w*64 + p*4, x); }
    if (p == 0) {
        if (n0) atomicAdd(deg + rr.x, v.x);
        if (n1) atomicAdd(deg + rr.y, v.y);
        if (n2) atomicAdd(deg + rr.z, v.z);
        if (n3) atomicAdd(deg + rr.w, v.w);
    }
}

// ---------------- fused mid: matmul_featW + rel_heavy --------------------------
__global__ void k_mid(const float* __restrict__ Wm, const float* __restrict__ item_emb) {
    int bx = blockIdx.x;
    if (bx < NB_MM) {
        __shared__ float4 w_s[64*16];
        __shared__ float4 a_s[16*16];
        int tid = threadIdx.x;
        const float4* W4 = reinterpret_cast<const float4*>(Wm);
        for (int t = tid; t < 64*16; t += 256) w_s[t] = W4[t];
        __syncthreads();
        int r = tid >> 4, j = tid & 15;
        for (int chunk = bx; chunk < NITEMS/16; chunk += NB_MM) {
            int row0 = chunk * 16;
            unsigned wbits = (g_ibit[row0 >> 5] >> (row0 & 31)) & 0xFFFFu;
            if (wbits == 0u) continue;
            a_s[r*16 + j] = reinterpret_cast<const float4*>(g_item_feat)[(row0 + r)*16 + j];
            __syncthreads();
            float4 acc = make_float4(0.f,0.f,0.f,0.f);
            #pragma unroll
            for (int kk = 0; kk < 16; kk++) {
                float4 a  = a_s[r*16 + kk];
                float4 w0 = w_s[(4*kk+0)*16 + j];
                float4 w1 = w_s[(4*kk+1)*16 + j];
                float4 w2 = w_s[(4*kk+2)*16 + j];
                float4 w3 = w_s[(4*kk+3)*16 + j];
                acc.x += a.x*w0.x + a.y*w1.x + a.z*w2.x + a.w*w3.x;
                acc.y += a.x*w0.y + a.y*w1.y + a.z*w2.y + a.w*w3.y;
                acc.z += a.x*w0.z + a.y*w1.z + a.z*w2.z + a.w*w3.z;
                acc.w += a.x*w0.w + a.y*w1.w + a.z*w2.w + a.w*w3.w;
            }
            if ((wbits >> r) & 1u)
                reinterpret_cast<float4*>(g_item_featW)[(row0 + r)*16 + j] = acc;
            __syncthreads();
        }
    } else {
        int bb = bx - NB_MM;
        int r = bb / NB_RH;
        int bxx = bb - r*NB_RH;
        int ne = g_cnt_rel[r];
        const int2* lst = g_crel + (size_t)r*NNZ_E;
        const float4* agg4 = reinterpret_cast<const float4*>(g_item_agg + (size_t)r*IE);
        const float* deg = g_ig_deg + (size_t)r*NITEMS;
        int p = threadIdx.x & 15;
        int lane_entry = (bxx * 256 + threadIdx.x) >> 4;
        const int stride = (NB_RH * 256) >> 4;
        for (int idx = lane_entry; idx < ne; idx += stride) {
            int2 ent = lst[idx];
            int slot = ent.x, col = ent.y;
            float4 ie = reinterpret_cast<const float4*>(item_emb)[(size_t)col*16 + p];
            float4 ag = agg4[(size_t)col*16 + p];
            float inv = 1.0f / (__ldg(&deg[col]) + EPSF);
            ag.x *= inv; ag.y *= inv; ag.z *= inv; ag.w *= inv;
            float* dst = g_uacc + ((size_t)r*BB + slot)*128;
            red_add_v4(dst + p*4, ie);
            red_add_v4(dst + 64 + p*4, ag);
        }
    }
}

// ---------------- slot-tiled proj (y<3, 16 slots/block) + userW (y==3) ---------
__global__ void k_projG(const float* __restrict__ Wb_all, const float* __restrict__ Wp_all,
                        const float* __restrict__ Wm, const float* __restrict__ mgnn) {
    int tid = threadIdx.x;          // 256
    if (blockIdx.y == RREL) {
        // u2 = user_feature @ W, 16 slots per block
        __shared__ float wm[64*64];      // 16KB
        __shared__ float uf[16*64];      // 4KB
        int slot0 = blockIdx.x * 16;
        for (int idx = tid; idx < 4096; idx += 256) wm[idx] = Wm[idx];
        float m0 = mgnn[0], m1 = mgnn[1], m2 = mgnn[2];
        for (int idx = tid; idx < 16*64; idx += 256) {
            int s = idx >> 6, j = idx & 63;
            int slot = slot0 + s;
            float d0 = g_udeg[slot], d1 = g_udeg[BB+slot], d2 = g_udeg[2*BB+slot];
            float total = m0*d0 + m1*d1 + m2*d2;
            float c0 = m0*d0/(d0+EPSF), c1 = m1*d1/(d1+EPSF), c2 = m2*d2/(d2+EPSF);
            float v = c0*g_uacc[(size_t)slot*128 + j]
                    + c1*g_uacc[((size_t)BB+slot)*128 + j]
                    + c2*g_uacc[((size_t)2*BB+slot)*128 + j];
            uf[idx] = v / (total + EPSF);
        }
        __syncthreads();
        // 16 slots x 64 outputs = 1024 tasks, 4 per thread
        for (int idx = tid; idx < 16*64; idx += 256) {
            int s = idx >> 6, j = idx & 63;
            float acc = 0.f;
            #pragma unroll 8
            for (int k = 0; k < 64; k++) acc += uf[s*64 + k] * wm[k*64 + j];
            g_u2[(size_t)(slot0 + s)*64 + j] = acc;
        }
        return;
    }
    // proj for 16 slots: s_mid = [s_in_a | s_in_b @ Wp]; full = s_mid @ Wb;
    // out = [full_a | Wp @ full_b]
    __shared__ float wp[64*64];      // 16KB
    __shared__ float s_mid[16*128];  // 8KB
    __shared__ float wtile[32*128];  // 16KB
    __shared__ float s_pr[16*128];   // 8KB
    int r = blockIdx.y;
    int slot0 = blockIdx.x * 16;
    const float* Wb = Wb_all + (size_t)r*16384;
    const float* Wp = Wp_all + (size_t)r*4096;
    for (int idx = tid; idx < 4096; idx += 256) wp[idx] = Wp[idx];
    // stage s_in into s_pr temporarily
    for (int idx = tid; idx < 16*128; idx += 256) {
        int s = idx >> 7, k = idx & 127;
        int slot = slot0 + s;
        s_pr[idx] = g_uacc[((size_t)r*BB + slot)*128 + k] / (g_udeg[r*BB + slot] + EPSF);
    }
    __syncthreads();
    // s_mid: first 64 copy, last 64 = s_in[64:] @ Wp
    for (int idx = tid; idx < 16*128; idx += 256) {
        int s = idx >> 7, j = idx & 127;
        float v;
        if (j < 64) {
            v = s_pr[s*128 + j];
        } else {
            int m = j - 64;
            float a = 0.f;
            #pragma unroll 8
            for (int k = 0; k < 64; k++) a += s_pr[s*128 + 64 + k] * wp[k*64 + m];
            v = a;
        }
        s_mid[idx] = v;
    }
    __syncthreads();
    // full = s_mid @ Wb, streaming Wb in 32x128 tiles; each thread owns 8 outputs
    {
        int s = tid >> 4;            // 0..15
        int j0 = (tid & 15) * 8;     // 8 consecutive cols
        float acc[8];
        #pragma unroll
        for (int jj = 0; jj < 8; jj++) acc[jj] = 0.f;
        for (int kt = 0; kt < 128; kt += 32) {
            for (int idx = tid; idx < 32*128; idx += 256)
                wtile[idx] = Wb[(kt + (idx >> 7))*128 + (idx & 127)];
            __syncthreads();
            #pragma unroll 4
            for (int kk = 0; kk < 32; kk++) {
                float a = s_mid[s*128 + kt + kk];
                #pragma unroll
                for (int jj = 0; jj < 8; jj++) acc[jj] += a * wtile[kk*128 + j0 + jj];
            }
            __syncthreads();
        }
        #pragma unroll
        for (int jj = 0; jj < 8; jj++) s_pr[s*128 + j0 + jj] = acc[jj];
    }
    __syncthreads();
    // out: first 64 copy, last 64 = Wp @ full[64:]
    for (int idx = tid; idx < 16*128; idx += 256) {
        int s = idx >> 7, j = idx & 127;
        float v;
        if (j < 64) {
            v = s_pr[s*128 + j];
        } else {
            int k = j - 64;
            float a = 0.f;
            #pragma unroll 8
            for (int jj = 0; jj < 64; jj++) a += wp[k*64 + jj] * s_pr[s*128 + 64 + jj];
            v = a;
        }
        g_proj[((size_t)r*BB + slot0 + s)*128 + j] = v;
    }
}

// ---------------- fused score1 + score2 + item L2 ----------------
__global__ void k_score(const int* __restrict__ user, const int* __restrict__ item,
                        const float* __restrict__ user_emb, const float* __restrict__ item_emb,
                        float* __restrict__ out) {
    int idx = blockIdx.x * blockDim.x + threadIdx.x;
    float n2 = 0.f;
    if (idx < BB*KK) {
        int b = idx / KK;
        int uid = user[b];
        int slot = g_map[uid];
        int it = item[idx];
        const float4* ue  = reinterpret_cast<const float4*>(user_emb) + (size_t)uid*16;
        const float4* u2  = reinterpret_cast<const float4*>(g_u2) + (size_t)slot*16;
        const float4* ie  = reinterpret_cast<const float4*>(item_emb) + (size_t)it*16;
        const float4* ifw = reinterpret_cast<const float4*>(g_item_featW) + (size_t)it*16;
        float s = 0.f;
        float4 ier[16];
        #pragma unroll
        for (int t = 0; t < 16; t++) {
            float4 a = ue[t], c = ie[t];
            ier[t] = c;
            s  += a.x*c.x + a.y*c.y + a.z*c.z + a.w*c.w;
            n2 += c.x*c.x + c.y*c.y + c.z*c.z + c.w*c.w;
        }
        #pragma unroll
        for (int t = 0; t < 16; t++) {
            float4 a = u2[t], c = ifw[t];
            s  += a.x*c.x + a.y*c.y + a.z*c.z + a.w*c.w;
            n2 += c.x*c.x + c.y*c.y + c.z*c.z + c.w*c.w;
        }
        float s2 = 0.f;
        #pragma unroll
        for (int r = 0; r < RREL; r++) {
            const float4* pr = reinterpret_cast<const float4*>(g_proj) + ((size_t)r*BB + slot)*32;
            const float4* ag = reinterpret_cast<const float4*>(g_item_agg + (size_t)r*IE) + (size_t)it*16;
            float dinv = 1.0f / (g_ig_deg[r*NITEMS + it] + EPSF);
            #pragma unroll
            for (int t = 0; t < 16; t++) {
                float4 a = pr[t], c = ier[t];
                s2 += a.x*c.x + a.y*c.y + a.z*c.z + a.w*c.w;
            }
            #pragma unroll
            for (int t = 0; t < 16; t++) {
                float4 a = pr[16+t], c = ag[t];
                s2 += dinv * (a.x*c.x + a.y*c.y + a.z*c.z + a.w*c.w);
            }
        }
        out[idx] = s + SCORE2_SCALE * s2;
    }
    __shared__ float red[256];
    red[threadIdx.x] = n2;
    __syncthreads();
    for (int s = 128; s > 0; s >>= 1) {
        if (threadIdx.x < s) red[threadIdx.x] += red[threadIdx.x + s];
        __syncthreads();
    }
    if (threadIdx.x == 0) atomicAdd(&g_l2i, (double)red[0]);
}

// ---------------- user-side L2 + final output element ----------------
__global__ void k_l2final(const int* __restrict__ user, const float* __restrict__ user_emb,
                          float* __restrict__ out, int out_n) {
    int b = threadIdx.x;   // 512
    int uid = user[b];
    int slot = g_map[uid];
    const float4* ue = reinterpret_cast<const float4*>(user_emb) + (size_t)uid*16;
    const float4* u2 = reinterpret_cast<const float4*>(g_u2) + (size_t)slot*16;
    float n2 = 0.f;
    #pragma unroll
    for (int t = 0; t < 16; t++) {
        float4 a = ue[t]; n2 += a.x*a.x + a.y*a.y + a.z*a.z + a.w*a.w;
        float4 c = u2[t]; n2 += c.x*c.x + c.y*c.y + c.z*c.z + c.w*c.w;
    }
    __shared__ float red[512];
    red[b] = n2;
    __syncthreads();
    for (int s = 256; s > 0; s >>= 1) {
        if (b < s) red[b] += red[b + s];
        __syncthreads();
    }
    if (b == 0 && out_n > BB*KK) {
        out[BB*KK] = (float)((double)L2C * ((double)KK * (double)red[0] + g_l2i));
    }
}

// ---------------- launch (fork-join: prescan overlaps zero_big + train scatter) --
extern "C" void kernel_launch(void* const* d_in, const int* in_sizes, int n_in,
                              void* d_out, int out_size) {
    const int*   user       = (const int*)  d_in[0];
    const int*   item       = (const int*)  d_in[1];
    const int*   rel_rows   = (const int*)  d_in[2];
    const int*   rel_cols   = (const int*)  d_in[3];
    const int*   ig_rows    = (const int*)  d_in[4];
    const int*   ig_cols    = (const int*)  d_in[5];
    const float* ig_vals    = (const float*)d_in[6];
    const int*   train_rows = (const int*)  d_in[7];
    const int*   train_cols = (const int*)  d_in[8];
    const float* user_emb   = (const float*)d_in[9];
    const float* item_emb   = (const float*)d_in[10];
    const float* mgnn       = (const float*)d_in[11];
    const float* Wb         = (const float*)d_in[12];
    const float* Wp         = (const float*)d_in[13];
    const float* Wm         = (const float*)d_in[14];
    float* out = (float*)d_out;

    cudaStream_t s2;
    cudaStreamCreateWithFlags(&s2, cudaStreamNonBlocking);
    cudaEvent_t ev_map, ev_pre;
    cudaEventCreateWithFlags(&ev_map, cudaEventDisableTiming);
    cudaEventCreateWithFlags(&ev_pre, cudaEventDisableTiming);

    k_zero_small<<<(RREL*BB*128/4 + 255)/256, 256>>>();
    k_map<<<(BB*KK + 255)/256, 256>>>(user, item);
    cudaEventRecord(ev_map, 0);

    cudaStreamWaitEvent(s2, ev_map, 0);
    {
        dim3 grid((NNZ_E/4 + 255)/256, RREL);
        k_prescan_rel<<<grid, 256, 0, s2>>>(rel_rows, rel_cols);
    }
    cudaEventRecord(ev_pre, s2);

    k_zero_big<<<(RREL*IE/4 + 255)/256, 256>>>();
    k_scatter_tr<<<NB_TR, 256>>>(train_rows, train_cols, user_emb);

    cudaStreamWaitEvent(0, ev_pre, 0);
    k_scatter_ig<<<RREL*NB_IG, 256>>>(ig_rows, ig_cols, ig_vals, item_emb);

    k_mid<<<NB_MID, 256>>>(Wm, item_emb);

    {
        dim3 grid(32, RREL + 1);
        k_projG<<<grid, 256>>>(Wb, Wp, Wm, mgnn);
    }

    k_score<<<(BB*KK + 255)/256, 256>>>(user, item, user_emb, item_emb, out);
    k_l2final<<<1, BB>>>(user, user_emb, out, out_size);
}

// round 12
// speedup vs baseline: 1.0573x; 1.0573x over previous
#include <cuda_runtime.h>
#include <cstdint>

#define NUSERS 100000
#define NITEMS 50000
#define EMBED 64
#define RREL 3
#define NNZ_E 1000000
#define IG_NNZ_E 500000
#define BB 512
#define KK 100
#define EPSF 1e-8f
#define SCORE2_SCALE (0.5f/3.0f)
#define L2C 1e-4f

#define IE (NITEMS*EMBED)
#define UBW 3200
#define IBW 1600

#define NB_IG 7813                 // ceil(500000/4*16 / 256) per relation
#define NB_TR 15625                // 1000000/4*16 / 256
#define NB_MM 512
#define NB_RH 128
#define NB_MID (NB_MM + RREL*NB_RH)

// ---------------- device scratch (static, allocation-free) ----------------
__device__ __align__(16) float g_item_agg[RREL*IE];
__device__ __align__(16) float g_item_feat[IE];
__device__ __align__(16) float g_item_featW[IE];
__device__ __align__(16) float g_ig_deg[RREL*NITEMS];
__device__ __align__(16) int   g_map[NUSERS];
__device__ __align__(16) unsigned g_ubit[UBW];
__device__ __align__(16) unsigned g_ibit[IBW];
__device__ __align__(16) unsigned g_nbit[IBW];
__device__ __align__(16) float g_udeg[RREL*BB];
__device__ __align__(16) float g_uacc[RREL*BB*128];
__device__ __align__(16) float g_proj[RREL*BB*128];
__device__ __align__(16) float g_u2[BB*EMBED];
__device__ __align__(16) int2  g_crel[RREL*NNZ_E];
__device__ int g_cnt_rel[RREL];
__device__ double g_l2i;

__device__ __forceinline__ void red_add_v4(float* addr, float4 v) {
    asm volatile("red.global.add.v4.f32 [%0], {%1,%2,%3,%4};"
                 :: "l"(addr), "f"(v.x), "f"(v.y), "f"(v.z), "f"(v.w) : "memory");
}

// ---------------- zero: small control structures ----------------
__global__ void k_zero_small() {
    int idx = blockIdx.x * blockDim.x + threadIdx.x;
    float4 z4 = make_float4(0.f,0.f,0.f,0.f);
    if (idx < RREL*BB*128/4)   reinterpret_cast<float4*>(g_uacc)[idx] = z4;
    if (idx < RREL*BB)         g_udeg[idx] = 0.f;
    if (idx < NUSERS/4)        reinterpret_cast<int4*>(g_map)[idx] = make_int4(-1,-1,-1,-1);
    if (idx < UBW)             g_ubit[idx] = 0u;
    if (idx < IBW)             { g_ibit[idx] = 0u; g_nbit[idx] = 0u; }
    if (idx < RREL)            g_cnt_rel[idx] = 0;
    if (idx == 0)              g_l2i = 0.0;
}

// ---------------- zero: big embedding planes ----------------
__global__ void k_zero_big() {
    int idx = blockIdx.x * blockDim.x + threadIdx.x;   // RREL*IE/4 = 2.4M
    float4 z4 = make_float4(0.f,0.f,0.f,0.f);
    if (idx < RREL*IE/4)       reinterpret_cast<float4*>(g_item_agg)[idx] = z4;
    if (idx < IE/4)            reinterpret_cast<float4*>(g_item_feat)[idx] = z4;
    if (idx < RREL*NITEMS/4)   reinterpret_cast<float4*>(g_ig_deg)[idx] = z4;
}

// ---------------- build maps / bitmaps ----------------
__global__ void k_map(const int* __restrict__ user, const int* __restrict__ item) {
    int idx = blockIdx.x * blockDim.x + threadIdx.x;
    if (idx < BB) {
        int uid = user[idx];
        g_map[uid] = idx;
        atomicOr(&g_ubit[uid >> 5], 1u << (uid & 31));
    }
    if (idx < BB*KK) {
        int it = item[idx];
        atomicOr(&g_ibit[it >> 5], 1u << (it & 31));
        atomicOr(&g_nbit[it >> 5], 1u << (it & 31));
    }
}

// ---------------- prescan rel edges: warp-aggregated compaction ----------------
__global__ void k_prescan_rel(const int* __restrict__ rows_all, const int* __restrict__ cols_all) {
    int r = blockIdx.y;
    const int* rows = rows_all + (size_t)r*NNZ_E;
    const int* cols = cols_all + (size_t)r*NNZ_E;
    int g = blockIdx.x * blockDim.x + threadIdx.x;
    int lane = threadIdx.x & 31;
    bool inrange = (g < NNZ_E/4);
    int e0 = g * 4;
    int4 rr = inrange ? *reinterpret_cast<const int4*>(rows + e0) : make_int4(0,0,0,0);
    #pragma unroll
    for (int q = 0; q < 4; q++) {
        int row = (q==0)?rr.x:(q==1)?rr.y:(q==2)?rr.z:rr.w;
        bool pass = false;
        if (inrange) {
            unsigned w = __ldg(&g_ubit[row >> 5]);
            pass = (w >> (row & 31)) & 1u;
        }
        unsigned m = __ballot_sync(0xffffffffu, pass);
        if (m == 0) continue;
        int cnt = __popc(m);
        int leader = __ffs(m) - 1;
        int base = 0;
        if (lane == leader) base = atomicAdd(&g_cnt_rel[r], cnt);
        base = __shfl_sync(0xffffffffu, base, leader);
        if (pass) {
            int rank = __popc(m & ((1u << lane) - 1u));
            int slot = g_map[row];
            int col = __ldg(&cols[e0 + q]);
            g_crel[(size_t)r*NNZ_E + base + rank] = make_int2(slot, col);
            atomicAdd(&g_udeg[r*BB + slot], 1.0f);
            atomicOr(&g_nbit[col >> 5], 1u << (col & 31));
        }
    }
}

// ---------------- train scatter (only needs ibit + zeroed item_feat) ----------
__global__ void k_scatter_tr(const int* __restrict__ tr_rows, const int* __restrict__ tr_cols,
                             const float* __restrict__ user_emb) {
    int t = blockIdx.x * 256 + threadIdx.x;
    int g = t >> 4;
    if (g >= NNZ_E/4) return;
    int p = t & 15;
    int e0 = g * 4;
    int4 cc = *reinterpret_cast<const int4*>(tr_cols + e0);
    int4 rr = *reinterpret_cast<const int4*>(tr_rows + e0);
    const float4* E = reinterpret_cast<const float4*>(user_emb);
    bool b0 = (__ldg(&g_ibit[cc.x >> 5]) >> (cc.x & 31)) & 1u;
    bool b1 = (__ldg(&g_ibit[cc.y >> 5]) >> (cc.y & 31)) & 1u;
    bool b2 = (__ldg(&g_ibit[cc.z >> 5]) >> (cc.z & 31)) & 1u;
    bool b3 = (__ldg(&g_ibit[cc.w >> 5]) >> (cc.w & 31)) & 1u;
    if (b0) { float4 x = E[(size_t)rr.x*16 + p]; red_add_v4(g_item_feat + (size_t)cc.x*64 + p*4, x); }
    if (b1) { float4 x = E[(size_t)rr.y*16 + p]; red_add_v4(g_item_feat + (size_t)cc.y*64 + p*4, x); }
    if (b2) { float4 x = E[(size_t)rr.z*16 + p]; red_add_v4(g_item_feat + (size_t)cc.z*64 + p*4, x); }
    if (b3) { float4 x = E[(size_t)rr.w*16 + p]; red_add_v4(g_item_feat + (size_t)cc.w*64 + p*4, x); }
}

// ---------------- ig scatter, 3 relations flattened (needs nbit from prescan) --
__global__ void k_scatter_ig(const int* __restrict__ ig_rows_all, const int* __restrict__ ig_cols_all,
                             const float* __restrict__ ig_vals_all, const float* __restrict__ item_emb) {
    int bx = blockIdx.x;
    int r = bx / NB_IG;
    int bxx = bx - r*NB_IG;
    const int*   rows = ig_rows_all + (size_t)r*IG_NNZ_E;
    const int*   cols = ig_cols_all + (size_t)r*IG_NNZ_E;
    const float* vals = ig_vals_all + (size_t)r*IG_NNZ_E;
    float* agg = g_item_agg + (size_t)r*IE;
    float* deg = g_ig_deg + (size_t)r*NITEMS;
    int t = bxx * 256 + threadIdx.x;
    int g = t >> 4;
    if (g >= IG_NNZ_E/4) return;
    int p = t & 15;
    int e0 = g * 4;
    int4  rr = *reinterpret_cast<const int4*>(rows + e0);
    int4   c = *reinterpret_cast<const int4*>(cols + e0);
    float4 v = *reinterpret_cast<const float4*>(vals + e0);
    const float4* E = reinterpret_cast<const float4*>(item_emb);
    bool n0 = (__ldg(&g_nbit[rr.x >> 5]) >> (rr.x & 31)) & 1u;
    bool n1 = (__ldg(&g_nbit[rr.y >> 5]) >> (rr.y & 31)) & 1u;
    bool n2 = (__ldg(&g_nbit[rr.z >> 5]) >> (rr.z & 31)) & 1u;
    bool n3 = (__ldg(&g_nbit[rr.w >> 5]) >> (rr.w & 31)) & 1u;
    if (n0) { float4 x = E[(size_t)c.x*16 + p]; x.x*=v.x; x.y*=v.x; x.z*=v.x; x.w*=v.x;
              red_add_v4(agg + (size_t)rr.x*64 + p*4, x); }
    if (n1) { float4 x = E[(size_t)c.y*16 + p]; x.x*=v.y; x.y*=v.y; x.z*=v.y; x.w*=v.y;
              red_add_v4(agg + (size_t)rr.y*64 + p*4, x); }
    if (n2) { float4 x = E[(size_t)c.z*16 + p]; x.x*=v.z; x.y*=v.z; x.z*=v.z; x.w*=v.z;
              red_add_v4(agg + (size_t)rr.z*64 + p*4, x); }
    if (n3) { float4 x = E[(size_t)c.w*16 + p]; x.x*=v.w; x.y*=v.w; x.z*=v.w; x.w*=v.w;
              red_add_v4(agg + (size_t)rr.w*64 + p*4, x); }
    if (p == 0) {
        if (n0) atomicAdd(deg + rr.x, v.x);
        if (n1) atomicAdd(deg + rr.y, v.y);
        if (n2) atomicAdd(deg + rr.z, v.z);
        if (n3) atomicAdd(deg + rr.w, v.w);
    }
}

// ---------------- fused mid: matmul_featW + rel_heavy --------------------------
__global__ void k_mid(const float* __restrict__ Wm, const float* __restrict__ item_emb) {
    int bx = blockIdx.x;
    if (bx < NB_MM) {
        __shared__ float4 w_s[64*16];
        __shared__ float4 a_s[16*16];
        int tid = threadIdx.x;
        const float4* W4 = reinterpret_cast<const float4*>(Wm);
        for (int t = tid; t < 64*16; t += 256) w_s[t] = W4[t];
        __syncthreads();
        int r = tid >> 4, j = tid & 15;
        for (int chunk = bx; chunk < NITEMS/16; chunk += NB_MM) {
            int row0 = chunk * 16;
            unsigned wbits = (g_ibit[row0 >> 5] >> (row0 & 31)) & 0xFFFFu;
            if (wbits == 0u) continue;
            a_s[r*16 + j] = reinterpret_cast<const float4*>(g_item_feat)[(row0 + r)*16 + j];
            __syncthreads();
            float4 acc = make_float4(0.f,0.f,0.f,0.f);
            #pragma unroll
            for (int kk = 0; kk < 16; kk++) {
                float4 a  = a_s[r*16 + kk];
                float4 w0 = w_s[(4*kk+0)*16 + j];
                float4 w1 = w_s[(4*kk+1)*16 + j];
                float4 w2 = w_s[(4*kk+2)*16 + j];
                float4 w3 = w_s[(4*kk+3)*16 + j];
                acc.x += a.x*w0.x + a.y*w1.x + a.z*w2.x + a.w*w3.x;
                acc.y += a.x*w0.y + a.y*w1.y + a.z*w2.y + a.w*w3.y;
                acc.z += a.x*w0.z + a.y*w1.z + a.z*w2.z + a.w*w3.z;
                acc.w += a.x*w0.w + a.y*w1.w + a.z*w2.w + a.w*w3.w;
            }
            if ((wbits >> r) & 1u)
                reinterpret_cast<float4*>(g_item_featW)[(row0 + r)*16 + j] = acc;
            __syncthreads();
        }
    } else {
        int bb = bx - NB_MM;
        int r = bb / NB_RH;
        int bxx = bb - r*NB_RH;
        int ne = g_cnt_rel[r];
        const int2* lst = g_crel + (size_t)r*NNZ_E;
        const float4* agg4 = reinterpret_cast<const float4*>(g_item_agg + (size_t)r*IE);
        const float* deg = g_ig_deg + (size_t)r*NITEMS;
        int p = threadIdx.x & 15;
        int lane_entry = (bxx * 256 + threadIdx.x) >> 4;
        const int stride = (NB_RH * 256) >> 4;
        for (int idx = lane_entry; idx < ne; idx += stride) {
            int2 ent = lst[idx];
            int slot = ent.x, col = ent.y;
            float4 ie = reinterpret_cast<const float4*>(item_emb)[(size_t)col*16 + p];
            float4 ag = agg4[(size_t)col*16 + p];
            float inv = 1.0f / (__ldg(&deg[col]) + EPSF);
            ag.x *= inv; ag.y *= inv; ag.z *= inv; ag.w *= inv;
            float* dst = g_uacc + ((size_t)r*BB + slot)*128;
            red_add_v4(dst + p*4, ie);
            red_add_v4(dst + 64 + p*4, ag);
        }
    }
}

// ---------------- proj (y<3) + userW (y==3)  [round-10 version] ----------------
__global__ void k_proj(const float* __restrict__ Wb_all, const float* __restrict__ Wp_all,
                       const float* __restrict__ Wm, const float* __restrict__ mgnn) {
    if (blockIdx.y == RREL) {
        __shared__ float uf[64];
        int slot = blockIdx.x, j = threadIdx.x;
        if (j < 64) {
            float m0 = mgnn[0], m1 = mgnn[1], m2 = mgnn[2];
            float d0 = g_udeg[slot], d1 = g_udeg[BB+slot], d2 = g_udeg[2*BB+slot];
            float total = m0*d0 + m1*d1 + m2*d2;
            float c0 = m0*d0/(d0+EPSF), c1 = m1*d1/(d1+EPSF), c2 = m2*d2/(d2+EPSF);
            float v = c0*g_uacc[(size_t)slot*128 + j]
                    + c1*g_uacc[((size_t)BB+slot)*128 + j]
                    + c2*g_uacc[((size_t)2*BB+slot)*128 + j];
            uf[j] = v / (total + EPSF);
        }
        __syncthreads();
        if (j < 64) {
            float acc = 0.f;
            #pragma unroll 8
            for (int k = 0; k < 64; k++) acc += uf[k] * Wm[k*64 + j];
            g_u2[slot*64 + j] = acc;
        }
        return;
    }
    __shared__ float s_in[128], s_mid[128], s_pr[128];
    int r = blockIdx.y, slot = blockIdx.x, j = threadIdx.x;
    const float* Wb = Wb_all + (size_t)r*128*128;
    const float* Wp = Wp_all + (size_t)r*64*64;
    float inv = 1.0f / (g_udeg[r*BB + slot] + EPSF);
    s_in[j] = g_uacc[((size_t)r*BB + slot)*128 + j] * inv;
    __syncthreads();
    if (j < 64) {
        s_mid[j] = s_in[j];
    } else {
        int m = j - 64;
        float a = 0.f;
        #pragma unroll 8
        for (int k = 0; k < 64; k++) a += s_in[64+k] * Wp[k*64 + m];
        s_mid[j] = a;
    }
    __syncthreads();
    float pr = 0.f;
    #pragma unroll 8
    for (int k = 0; k < 128; k++) pr += s_mid[k] * Wb[k*128 + j];
    s_pr[j] = pr;
    __syncthreads();
    float outv;
    if (j < 64) {
        outv = pr;
    } else {
        int k = j - 64;
        float a = 0.f;
        #pragma unroll 8
        for (int jj = 0; jj < 64; jj++) a += Wp[k*64 + jj] * s_pr[64+jj];
        outv = a;
    }
    g_proj[((size_t)r*BB + slot)*128 + j] = outv;
}

// ---------------- per-user-block score: 512 blocks x 128 threads ----------------
__global__ void k_score(const int* __restrict__ user, const int* __restrict__ item,
                        const float* __restrict__ user_emb, const float* __restrict__ item_emb,
                        float* __restrict__ out) {
    __shared__ float s_ue[64];
    __shared__ float s_u2[64];
    __shared__ float s_pr[RREL][128];
    int b = blockIdx.x;
    int tid = threadIdx.x;           // 128
    int uid = __ldg(&user[b]);
    int slot = g_map[uid];
    if (tid < 64) {
        s_ue[tid] = __ldg(&user_emb[(size_t)uid*64 + tid]);
        s_u2[tid] = g_u2[(size_t)slot*64 + tid];
    }
    #pragma unroll
    for (int r = 0; r < RREL; r++)
        s_pr[r][tid] = g_proj[((size_t)r*BB + slot)*128 + tid];
    __syncthreads();

    int w = tid >> 5, lane = tid & 31;
    float n2 = 0.f;
    for (int k = w; k < KK; k += 4) {
        int it = __ldg(&item[b*KK + k]);
        const float2* ie2  = reinterpret_cast<const float2*>(item_emb + (size_t)it*64);
        const float2* if2  = reinterpret_cast<const float2*>(g_item_featW + (size_t)it*64);
        float2 e = __ldg(&ie2[lane]);   // dims 2*lane, 2*lane+1
        float2 f = if2[lane];
        int d0 = 2*lane, d1 = 2*lane + 1;
        float s = s_ue[d0]*e.x + s_ue[d1]*e.y + s_u2[d0]*f.x + s_u2[d1]*f.y;
        n2 += e.x*e.x + e.y*e.y + f.x*f.x + f.y*f.y;
        float s2 = 0.f;
        #pragma unroll
        for (int r = 0; r < RREL; r++) {
            const float2* ag2 = reinterpret_cast<const float2*>(g_item_agg + (size_t)r*IE + (size_t)it*64);
            float2 a = ag2[lane];
            float dinv = 1.0f / (g_ig_deg[r*NITEMS + it] + EPSF);
            s2 += s_pr[r][d0]*e.x + s_pr[r][d1]*e.y
                + dinv * (s_pr[r][64+d0]*a.x + s_pr[r][64+d1]*a.y);
        }
        float tot = s + SCORE2_SCALE * s2;
        // warp reduce
        #pragma unroll
        for (int off = 16; off > 0; off >>= 1)
            tot += __shfl_xor_sync(0xffffffffu, tot, off);
        if (lane == 0) out[b*KK + k] = tot;
    }
    // block-reduce n2 -> g_l2i
    __shared__ float red[128];
    red[tid] = n2;
    __syncthreads();
    for (int s = 64; s > 0; s >>= 1) {
        if (tid < s) red[tid] += red[tid + s];
        __syncthreads();
    }
    if (tid == 0) atomicAdd(&g_l2i, (double)red[0]);
}

// ---------------- user-side L2 + final output element ----------------
__global__ void k_l2final(const int* __restrict__ user, const float* __restrict__ user_emb,
                          float* __restrict__ out, int out_n) {
    int b = threadIdx.x;   // 512
    int uid = user[b];
    int slot = g_map[uid];
    const float4* ue = reinterpret_cast<const float4*>(user_emb) + (size_t)uid*16;
    const float4* u2 = reinterpret_cast<const float4*>(g_u2) + (size_t)slot*16;
    float n2 = 0.f;
    #pragma unroll
    for (int t = 0; t < 16; t++) {
        float4 a = ue[t]; n2 += a.x*a.x + a.y*a.y + a.z*a.z + a.w*a.w;
        float4 c = u2[t]; n2 += c.x*c.x + c.y*c.y + c.z*c.z + c.w*c.w;
    }
    __shared__ float red[512];
    red[b] = n2;
    __syncthreads();
    for (int s = 256; s > 0; s >>= 1) {
        if (b < s) red[b] += red[b + s];
        __syncthreads();
    }
    if (b == 0 && out_n > BB*KK) {
        out[BB*KK] = (float)((double)L2C * ((double)KK * (double)red[0] + g_l2i));
    }
}

// ---------------- launch (fork-join: prescan overlaps zero_big + train scatter) --
extern "C" void kernel_launch(void* const* d_in, const int* in_sizes, int n_in,
                              void* d_out, int out_size) {
    const int*   user       = (const int*)  d_in[0];
    const int*   item       = (const int*)  d_in[1];
    const int*   rel_rows   = (const int*)  d_in[2];
    const int*   rel_cols   = (const int*)  d_in[3];
    const int*   ig_rows    = (const int*)  d_in[4];
    const int*   ig_cols    = (const int*)  d_in[5];
    const float* ig_vals    = (const float*)d_in[6];
    const int*   train_rows = (const int*)  d_in[7];
    const int*   train_cols = (const int*)  d_in[8];
    const float* user_emb   = (const float*)d_in[9];
    const float* item_emb   = (const float*)d_in[10];
    const float* mgnn       = (const float*)d_in[11];
    const float* Wb         = (const float*)d_in[12];
    const float* Wp         = (const float*)d_in[13];
    const float* Wm         = (const float*)d_in[14];
    float* out = (float*)d_out;

    cudaStream_t s2;
    cudaStreamCreateWithFlags(&s2, cudaStreamNonBlocking);
    cudaEvent_t ev_map, ev_pre;
    cudaEventCreateWithFlags(&ev_map, cudaEventDisableTiming);
    cudaEventCreateWithFlags(&ev_pre, cudaEventDisableTiming);

    k_zero_small<<<(RREL*BB*128/4 + 255)/256, 256>>>();
    k_map<<<(BB*KK + 255)/256, 256>>>(user, item);
    cudaEventRecord(ev_map, 0);

    cudaStreamWaitEvent(s2, ev_map, 0);
    {
        dim3 grid((NNZ_E/4 + 255)/256, RREL);
        k_prescan_rel<<<grid, 256, 0, s2>>>(rel_rows, rel_cols);
    }
    cudaEventRecord(ev_pre, s2);

    k_zero_big<<<(RREL*IE/4 + 255)/256, 256>>>();
    k_scatter_tr<<<NB_TR, 256>>>(train_rows, train_cols, user_emb);

    cudaStreamWaitEvent(0, ev_pre, 0);
    k_scatter_ig<<<RREL*NB_IG, 256>>>(ig_rows, ig_cols, ig_vals, item_emb);

    k_mid<<<NB_MID, 256>>>(Wm, item_emb);

    {
        dim3 grid(BB, RREL + 1);
        k_proj<<<grid, 128>>>(Wb, Wp, Wm, mgnn);
    }

    k_score<<<BB, 128>>>(user, item, user_emb, item_emb, out);
    k_l2final<<<1, BB>>>(user, user_emb, out, out_size);
}

// round 13
// speedup vs baseline: 1.1098x; 1.0497x over previous
#include <cuda_runtime.h>
#include <cstdint>

#define NUSERS 100000
#define NITEMS 50000
#define EMBED 64
#define RREL 3
#define NNZ_E 1000000
#define IG_NNZ_E 500000
#define BB 512
#define KK 100
#define EPSF 1e-8f
#define SCORE2_SCALE (0.5f/3.0f)
#define L2C 1e-4f

#define IE (NITEMS*EMBED)
#define UBW 3200
#define IBW 1600

#define NB_IG 7813                 // ceil(500000/4*16 / 256) per relation
#define NB_TR 15625                // 1000000/4*16 / 256
#define NB_MM 512
#define NB_RH 128
#define NB_MID (NB_MM + RREL*NB_RH)
#define NB_SCORE 200               // ceil(51200/256)

// ---------------- device scratch (static, allocation-free) ----------------
__device__ __align__(16) float g_item_agg[RREL*IE];
__device__ __align__(16) float g_item_feat[IE];
__device__ __align__(16) float g_item_featW[IE];
__device__ __align__(16) float g_ig_deg[RREL*NITEMS];
__device__ __align__(16) int   g_map[NUSERS];        // NOT initialized: all reads gated
__device__ __align__(16) unsigned g_ubit[UBW];
__device__ __align__(16) unsigned g_ibit[IBW];
__device__ __align__(16) unsigned g_nbit[IBW];
__device__ __align__(16) float g_udeg[RREL*BB];
__device__ __align__(16) float g_uacc[RREL*BB*128];
__device__ __align__(16) float g_proj[RREL*BB*128];
__device__ __align__(16) float g_u2[BB*EMBED];
__device__ __align__(16) int2  g_crel[RREL*NNZ_E];
__device__ int g_cnt_rel[RREL];
__device__ double g_l2i;
__device__ int g_done;

__device__ __forceinline__ void red_add_v4(float* addr, float4 v) {
    asm volatile("red.global.add.v4.f32 [%0], {%1,%2,%3,%4};"
                 :: "l"(addr), "f"(v.x), "f"(v.y), "f"(v.z), "f"(v.w) : "memory");
}

// ---------------- one merged zero kernel ----------------
__global__ void k_zero() {
    int idx = blockIdx.x * blockDim.x + threadIdx.x;   // 9375*256 = 2.4M
    float4 z4 = make_float4(0.f,0.f,0.f,0.f);
    if (idx < RREL*IE/4)       reinterpret_cast<float4*>(g_item_agg)[idx] = z4;
    if (idx < IE/4)            reinterpret_cast<float4*>(g_item_feat)[idx] = z4;
    if (idx < RREL*NITEMS/4)   reinterpret_cast<float4*>(g_ig_deg)[idx] = z4;
    if (idx < RREL*BB*128/4)   reinterpret_cast<float4*>(g_uacc)[idx] = z4;
    if (idx < RREL*BB)         g_udeg[idx] = 0.f;
    if (idx < UBW)             g_ubit[idx] = 0u;
    if (idx < IBW)             { g_ibit[idx] = 0u; g_nbit[idx] = 0u; }
    if (idx < RREL)            g_cnt_rel[idx] = 0;
    if (idx == 0)              { g_l2i = 0.0; g_done = 0; }
}

// ---------------- build maps / bitmaps ----------------
__global__ void k_map(const int* __restrict__ user, const int* __restrict__ item) {
    int idx = blockIdx.x * blockDim.x + threadIdx.x;
    if (idx < BB) {
        int uid = user[idx];
        g_map[uid] = idx;
        atomicOr(&g_ubit[uid >> 5], 1u << (uid & 31));
    }
    if (idx < BB*KK) {
        int it = item[idx];
        atomicOr(&g_ibit[it >> 5], 1u << (it & 31));
        atomicOr(&g_nbit[it >> 5], 1u << (it & 31));
    }
}

// ---------------- prescan rel edges: warp-aggregated compaction ----------------
__global__ void k_prescan_rel(const int* __restrict__ rows_all, const int* __restrict__ cols_all) {
    int r = blockIdx.y;
    const int* rows = rows_all + (size_t)r*NNZ_E;
    const int* cols = cols_all + (size_t)r*NNZ_E;
    int g = blockIdx.x * blockDim.x + threadIdx.x;
    int lane = threadIdx.x & 31;
    bool inrange = (g < NNZ_E/4);
    int e0 = g * 4;
    int4 rr = inrange ? *reinterpret_cast<const int4*>(rows + e0) : make_int4(0,0,0,0);
    #pragma unroll
    for (int q = 0; q < 4; q++) {
        int row = (q==0)?rr.x:(q==1)?rr.y:(q==2)?rr.z:rr.w;
        bool pass = false;
        if (inrange) {
            unsigned w = __ldg(&g_ubit[row >> 5]);
            pass = (w >> (row & 31)) & 1u;
        }
        unsigned m = __ballot_sync(0xffffffffu, pass);
        if (m == 0) continue;
        int cnt = __popc(m);
        int leader = __ffs(m) - 1;
        int base = 0;
        if (lane == leader) base = atomicAdd(&g_cnt_rel[r], cnt);
        base = __shfl_sync(0xffffffffu, base, leader);
        if (pass) {
            int rank = __popc(m & ((1u << lane) - 1u));
            int slot = g_map[row];      // gated by ubit: written by k_map
            int col = __ldg(&cols[e0 + q]);
            g_crel[(size_t)r*NNZ_E + base + rank] = make_int2(slot, col);
            atomicAdd(&g_udeg[r*BB + slot], 1.0f);
            atomicOr(&g_nbit[col >> 5], 1u << (col & 31));
        }
    }
}

// ---------------- train scatter (only needs ibit + zeroed item_feat) ----------
__global__ void k_scatter_tr(const int* __restrict__ tr_rows, const int* __restrict__ tr_cols,
                             const float* __restrict__ user_emb) {
    int t = blockIdx.x * 256 + threadIdx.x;
    int g = t >> 4;
    if (g >= NNZ_E/4) return;
    int p = t & 15;
    int e0 = g * 4;
    int4 cc = *reinterpret_cast<const int4*>(tr_cols + e0);
    int4 rr = *reinterpret_cast<const int4*>(tr_rows + e0);
    const float4* E = reinterpret_cast<const float4*>(user_emb);
    bool b0 = (__ldg(&g_ibit[cc.x >> 5]) >> (cc.x & 31)) & 1u;
    bool b1 = (__ldg(&g_ibit[cc.y >> 5]) >> (cc.y & 31)) & 1u;
    bool b2 = (__ldg(&g_ibit[cc.z >> 5]) >> (cc.z & 31)) & 1u;
    bool b3 = (__ldg(&g_ibit[cc.w >> 5]) >> (cc.w & 31)) & 1u;
    if (b0) { float4 x = E[(size_t)rr.x*16 + p]; red_add_v4(g_item_feat + (size_t)cc.x*64 + p*4, x); }
    if (b1) { float4 x = E[(size_t)rr.y*16 + p]; red_add_v4(g_item_feat + (size_t)cc.y*64 + p*4, x); }
    if (b2) { float4 x = E[(size_t)rr.z*16 + p]; red_add_v4(g_item_feat + (size_t)cc.z*64 + p*4, x); }
    if (b3) { float4 x = E[(size_t)rr.w*16 + p]; red_add_v4(g_item_feat + (size_t)cc.w*64 + p*4, x); }
}

// ---------------- ig scatter, 3 relations flattened (needs nbit from prescan) --
__global__ void k_scatter_ig(const int* __restrict__ ig_rows_all, const int* __restrict__ ig_cols_all,
                             const float* __restrict__ ig_vals_all, const float* __restrict__ item_emb) {
    int bx = blockIdx.x;
    int r = bx / NB_IG;
    int bxx = bx - r*NB_IG;
    const int*   rows = ig_rows_all + (size_t)r*IG_NNZ_E;
    const int*   cols = ig_cols_all + (size_t)r*IG_NNZ_E;
    const float* vals = ig_vals_all + (size_t)r*IG_NNZ_E;
    float* agg = g_item_agg + (size_t)r*IE;
    float* deg = g_ig_deg + (size_t)r*NITEMS;
    int t = bxx * 256 + threadIdx.x;
    int g = t >> 4;
    if (g >= IG_NNZ_E/4) return;
    int p = t & 15;
    int e0 = g * 4;
    int4  rr = *reinterpret_cast<const int4*>(rows + e0);
    int4   c = *reinterpret_cast<const int4*>(cols + e0);
    float4 v = *reinterpret_cast<const float4*>(vals + e0);
    const float4* E = reinterpret_cast<const float4*>(item_emb);
    bool n0 = (__ldg(&g_nbit[rr.x >> 5]) >> (rr.x & 31)) & 1u;
    bool n1 = (__ldg(&g_nbit[rr.y >> 5]) >> (rr.y & 31)) & 1u;
    bool n2 = (__ldg(&g_nbit[rr.z >> 5]) >> (rr.z & 31)) & 1u;
    bool n3 = (__ldg(&g_nbit[rr.w >> 5]) >> (rr.w & 31)) & 1u;
    if (n0) { float4 x = E[(size_t)c.x*16 + p]; x.x*=v.x; x.y*=v.x; x.z*=v.x; x.w*=v.x;
              red_add_v4(agg + (size_t)rr.x*64 + p*4, x); }
    if (n1) { float4 x = E[(size_t)c.y*16 + p]; x.x*=v.y; x.y*=v.y; x.z*=v.y; x.w*=v.y;
              red_add_v4(agg + (size_t)rr.y*64 + p*4, x); }
    if (n2) { float4 x = E[(size_t)c.z*16 + p]; x.x*=v.z; x.y*=v.z; x.z*=v.z; x.w*=v.z;
              red_add_v4(agg + (size_t)rr.z*64 + p*4, x); }
    if (n3) { float4 x = E[(size_t)c.w*16 + p]; x.x*=v.w; x.y*=v.w; x.z*=v.w; x.w*=v.w;
              red_add_v4(agg + (size_t)rr.w*64 + p*4, x); }
    if (p == 0) {
        if (n0) atomicAdd(deg + rr.x, v.x);
        if (n1) atomicAdd(deg + rr.y, v.y);
        if (n2) atomicAdd(deg + rr.z, v.z);
        if (n3) atomicAdd(deg + rr.w, v.w);
    }
}

// ---------------- fused mid: matmul_featW + rel_heavy --------------------------
__global__ void k_mid(const float* __restrict__ Wm, const float* __restrict__ item_emb) {
    int bx = blockIdx.x;
    if (bx < NB_MM) {
        __shared__ float4 w_s[64*16];
        __shared__ float4 a_s[16*16];
        int tid = threadIdx.x;
        const float4* W4 = reinterpret_cast<const float4*>(Wm);
        for (int t = tid; t < 64*16; t += 256) w_s[t] = W4[t];
        __syncthreads();
        int r = tid >> 4, j = tid & 15;
        for (int chunk = bx; chunk < NITEMS/16; chunk += NB_MM) {
            int row0 = chunk * 16;
            unsigned wbits = (g_ibit[row0 >> 5] >> (row0 & 31)) & 0xFFFFu;
            if (wbits == 0u) continue;
            a_s[r*16 + j] = reinterpret_cast<const float4*>(g_item_feat)[(row0 + r)*16 + j];
            __syncthreads();
            float4 acc = make_float4(0.f,0.f,0.f,0.f);
            #pragma unroll
            for (int kk = 0; kk < 16; kk++) {
                float4 a  = a_s[r*16 + kk];
                float4 w0 = w_s[(4*kk+0)*16 + j];
                float4 w1 = w_s[(4*kk+1)*16 + j];
                float4 w2 = w_s[(4*kk+2)*16 + j];
                float4 w3 = w_s[(4*kk+3)*16 + j];
                acc.x += a.x*w0.x + a.y*w1.x + a.z*w2.x + a.w*w3.x;
                acc.y += a.x*w0.y + a.y*w1.y + a.z*w2.y + a.w*w3.y;
                acc.z += a.x*w0.z + a.y*w1.z + a.z*w2.z + a.w*w3.z;
                acc.w += a.x*w0.w + a.y*w1.w + a.z*w2.w + a.w*w3.w;
            }
            if ((wbits >> r) & 1u)
                reinterpret_cast<float4*>(g_item_featW)[(row0 + r)*16 + j] = acc;
            __syncthreads();
        }
    } else {
        int bb = bx - NB_MM;
        int r = bb / NB_RH;
        int bxx = bb - r*NB_RH;
        int ne = g_cnt_rel[r];
        const int2* lst = g_crel + (size_t)r*NNZ_E;
        const float4* agg4 = reinterpret_cast<const float4*>(g_item_agg + (size_t)r*IE);
        const float* deg = g_ig_deg + (size_t)r*NITEMS;
        int p = threadIdx.x & 15;
        int lane_entry = (bxx * 256 + threadIdx.x) >> 4;
        const int stride = (NB_RH * 256) >> 4;
        for (int idx = lane_entry; idx < ne; idx += stride) {
            int2 ent = lst[idx];
            int slot = ent.x, col = ent.y;
            float4 ie = reinterpret_cast<const float4*>(item_emb)[(size_t)col*16 + p];
            float4 ag = agg4[(size_t)col*16 + p];
            float inv = 1.0f / (__ldg(&deg[col]) + EPSF);
            ag.x *= inv; ag.y *= inv; ag.z *= inv; ag.w *= inv;
            float* dst = g_uacc + ((size_t)r*BB + slot)*128;
            red_add_v4(dst + p*4, ie);
            red_add_v4(dst + 64 + p*4, ag);
        }
    }
}

// ---------------- proj (y<3) + userW (y==3) ----------------
__global__ void k_proj(const float* __restrict__ Wb_all, const float* __restrict__ Wp_all,
                       const float* __restrict__ Wm, const float* __restrict__ mgnn) {
    if (blockIdx.y == RREL) {
        __shared__ float uf[64];
        int slot = blockIdx.x, j = threadIdx.x;
        if (j < 64) {
            float m0 = mgnn[0], m1 = mgnn[1], m2 = mgnn[2];
            float d0 = g_udeg[slot], d1 = g_udeg[BB+slot], d2 = g_udeg[2*BB+slot];
            float total = m0*d0 + m1*d1 + m2*d2;
            float c0 = m0*d0/(d0+EPSF), c1 = m1*d1/(d1+EPSF), c2 = m2*d2/(d2+EPSF);
            float v = c0*g_uacc[(size_t)slot*128 + j]
                    + c1*g_uacc[((size_t)BB+slot)*128 + j]
                    + c2*g_uacc[((size_t)2*BB+slot)*128 + j];
            uf[j] = v / (total + EPSF);
        }
        __syncthreads();
        if (j < 64) {
            float acc = 0.f;
            #pragma unroll 8
            for (int k = 0; k < 64; k++) acc += uf[k] * Wm[k*64 + j];
            g_u2[slot*64 + j] = acc;
        }
        return;
    }
    __shared__ float s_in[128], s_mid[128], s_pr[128];
    int r = blockIdx.y, slot = blockIdx.x, j = threadIdx.x;
    const float* Wb = Wb_all + (size_t)r*128*128;
    const float* Wp = Wp_all + (size_t)r*64*64;
    float inv = 1.0f / (g_udeg[r*BB + slot] + EPSF);
    s_in[j] = g_uacc[((size_t)r*BB + slot)*128 + j] * inv;
    __syncthreads();
    if (j < 64) {
        s_mid[j] = s_in[j];
    } else {
        int m = j - 64;
        float a = 0.f;
        #pragma unroll 8
        for (int k = 0; k < 64; k++) a += s_in[64+k] * Wp[k*64 + m];
        s_mid[j] = a;
    }
    __syncthreads();
    float pr = 0.f;
    #pragma unroll 8
    for (int k = 0; k < 128; k++) pr += s_mid[k] * Wb[k*128 + j];
    s_pr[j] = pr;
    __syncthreads();
    float outv;
    if (j < 64) {
        outv = pr;
    } else {
        int k = j - 64;
        float a = 0.f;
        #pragma unroll 8
        for (int jj = 0; jj < 64; jj++) a += Wp[k*64 + jj] * s_pr[64+jj];
        outv = a;
    }
    g_proj[((size_t)r*BB + slot)*128 + j] = outv;
}

// ---------------- fused score1 + score2 + full L2 + final write ----------------
__global__ void k_score(const int* __restrict__ user, const int* __restrict__ item,
                        const float* __restrict__ user_emb, const float* __restrict__ item_emb,
                        float* __restrict__ out, int out_n) {
    int idx = blockIdx.x * blockDim.x + threadIdx.x;
    float n2 = 0.f;
    if (idx < BB*KK) {
        int b = idx / KK;
        int uid = user[b];
        int slot = g_map[uid];
        int it = item[idx];
        const float4* ue  = reinterpret_cast<const float4*>(user_emb) + (size_t)uid*16;
        const float4* u2  = reinterpret_cast<const float4*>(g_u2) + (size_t)slot*16;
        const float4* ie  = reinterpret_cast<const float4*>(item_emb) + (size_t)it*16;
        const float4* ifw = reinterpret_cast<const float4*>(g_item_featW) + (size_t)it*16;
        float s = 0.f;
        float4 ier[16];
        #pragma unroll
        for (int t = 0; t < 16; t++) {
            float4 a = ue[t], c = ie[t];
            ier[t] = c;
            s  += a.x*c.x + a.y*c.y + a.z*c.z + a.w*c.w;
            n2 += c.x*c.x + c.y*c.y + c.z*c.z + c.w*c.w;
        }
        #pragma unroll
        for (int t = 0; t < 16; t++) {
            float4 a = u2[t], c = ifw[t];
            s  += a.x*c.x + a.y*c.y + a.z*c.z + a.w*c.w;
            n2 += c.x*c.x + c.y*c.y + c.z*c.z + c.w*c.w;
        }
        float s2 = 0.f;
        #pragma unroll
        for (int r = 0; r < RREL; r++) {
            const float4* pr = reinterpret_cast<const float4*>(g_proj) + ((size_t)r*BB + slot)*32;
            const float4* ag = reinterpret_cast<const float4*>(g_item_agg + (size_t)r*IE) + (size_t)it*16;
            float dinv = 1.0f / (g_ig_deg[r*NITEMS + it] + EPSF);
            #pragma unroll
            for (int t = 0; t < 16; t++) {
                float4 a = pr[t], c = ier[t];
                s2 += a.x*c.x + a.y*c.y + a.z*c.z + a.w*c.w;
            }
            #pragma unroll
            for (int t = 0; t < 16; t++) {
                float4 a = pr[16+t], c = ag[t];
                s2 += dinv * (a.x*c.x + a.y*c.y + a.z*c.z + a.w*c.w);
            }
        }
        out[idx] = s + SCORE2_SCALE * s2;
    }
    // user-side L2: first 512 threads add KK * |u_g|^2
    if (idx < BB) {
        int uid = user[idx];
        int slot = g_map[uid];
        const float4* ue = reinterpret_cast<const float4*>(user_emb) + (size_t)uid*16;
        const float4* u2 = reinterpret_cast<const float4*>(g_u2) + (size_t)slot*16;
        float un = 0.f;
        #pragma unroll
        for (int t = 0; t < 16; t++) {
            float4 a = ue[t]; un += a.x*a.x + a.y*a.y + a.z*a.z + a.w*a.w;
            float4 c = u2[t]; un += c.x*c.x + c.y*c.y + c.z*c.z + c.w*c.w;
        }
        n2 += (float)KK * un;
    }
    __shared__ float red[256];
    red[threadIdx.x] = n2;
    __syncthreads();
    for (int s = 128; s > 0; s >>= 1) {
        if (threadIdx.x < s) red[threadIdx.x] += red[threadIdx.x + s];
        __syncthreads();
    }
    if (threadIdx.x == 0) {
        atomicAdd(&g_l2i, (double)red[0]);
        __threadfence();
        int old = atomicAdd(&g_done, 1);
        if (old == gridDim.x - 1) {
            // last block: all g_l2i contributions are visible
            double total = atomicAdd(&g_l2i, 0.0);
            if (out_n > BB*KK) out[BB*KK] = (float)((double)L2C * total);
        }
    }
}

// ---------------- launch (fork-join: prescan overlaps train scatter) --
extern "C" void kernel_launch(void* const* d_in, const int* in_sizes, int n_in,
                              void* d_out, int out_size) {
    const int*   user       = (const int*)  d_in[0];
    const int*   item       = (const int*)  d_in[1];
    const int*   rel_rows   = (const int*)  d_in[2];
    const int*   rel_cols   = (const int*)  d_in[3];
    const int*   ig_rows    = (const int*)  d_in[4];
    const int*   ig_cols    = (const int*)  d_in[5];
    const float* ig_vals    = (const float*)d_in[6];
    const int*   train_rows = (const int*)  d_in[7];
    const int*   train_cols = (const int*)  d_in[8];
    const float* user_emb   = (const float*)d_in[9];
    const float* item_emb   = (const float*)d_in[10];
    const float* mgnn       = (const float*)d_in[11];
    const float* Wb         = (const float*)d_in[12];
    const float* Wp         = (const float*)d_in[13];
    const float* Wm         = (const float*)d_in[14];
    float* out = (float*)d_out;

    cudaStream_t s2;
    cudaStreamCreateWithFlags(&s2, cudaStreamNonBlocking);
    cudaEvent_t ev_map, ev_pre;
    cudaEventCreateWithFlags(&ev_map, cudaEventDisableTiming);
    cudaEventCreateWithFlags(&ev_pre, cudaEventDisableTiming);

    k_zero<<<(RREL*IE/4 + 255)/256, 256>>>();
    k_map<<<(BB*KK + 255)/256, 256>>>(user, item);
    cudaEventRecord(ev_map, 0);

    // side stream: prescan (needs map/ubit/udeg/counters from zero+map)
    cudaStreamWaitEvent(s2, ev_map, 0);
    {
        dim3 grid((NNZ_E/4 + 255)/256, RREL);
        k_prescan_rel<<<grid, 256, 0, s2>>>(rel_rows, rel_cols);
    }
    cudaEventRecord(ev_pre, s2);

    // main stream: train scatter (needs ibit + zeroed item_feat)
    k_scatter_tr<<<NB_TR, 256>>>(train_rows, train_cols, user_emb);

    // join: ig scatter needs nbit from prescan
    cudaStreamWaitEvent(0, ev_pre, 0);
    k_scatter_ig<<<RREL*NB_IG, 256>>>(ig_rows, ig_cols, ig_vals, item_emb);

    k_mid<<<NB_MID, 256>>>(Wm, item_emb);

    {
        dim3 grid(BB, RREL + 1);
        k_proj<<<grid, 128>>>(Wb, Wp, Wm, mgnn);
    }

    k_score<<<NB_SCORE, 256>>>(user, item, user_emb, item_emb, out, out_size);
}

// round 15
// speedup vs baseline: 1.1174x; 1.0068x over previous
#include <cuda_runtime.h>
#include <cstdint>

#define NUSERS 100000
#define NITEMS 50000
#define EMBED 64
#define RREL 3
#define NNZ_E 1000000
#define IG_NNZ_E 500000
#define BB 512
#define KK 100
#define EPSF 1e-8f
#define SCORE2_SCALE (0.5f/3.0f)
#define L2C 1e-4f

#define IE (NITEMS*EMBED)
#define UBW 3200
#define IBW 1600

#define NB_IG 7813                 // ceil(500000/4*16 / 256) per relation
#define NB_TR 15625                // 1000000/4*16 / 256
#define NB_MM 512
#define NB_RH 128
#define NB_SCORE 200               // ceil(51200/256)

// ---------------- device scratch (static, allocation-free) ----------------
__device__ __align__(16) float g_item_agg[RREL*IE];
__device__ __align__(16) float g_item_feat[IE];
__device__ __align__(16) float g_item_featW[IE];
__device__ __align__(16) float g_ig_deg[RREL*NITEMS];
__device__ __align__(16) int   g_map[NUSERS];        // NOT initialized: all reads gated
__device__ __align__(16) unsigned g_ubit[UBW];
__device__ __align__(16) unsigned g_ibit[IBW];
__device__ __align__(16) unsigned g_nbit[IBW];
__device__ __align__(16) float g_udeg[RREL*BB];
__device__ __align__(16) float g_uacc[RREL*BB*128];
__device__ __align__(16) float g_proj[RREL*BB*128];
__device__ __align__(16) float g_u2[BB*EMBED];
__device__ __align__(16) int2  g_crel[RREL*NNZ_E];
__device__ int g_cnt_rel[RREL];
__device__ double g_l2i;
__device__ int g_done;

__device__ __forceinline__ void red_add_v4(float* addr, float4 v) {
    asm volatile("red.global.add.v4.f32 [%0], {%1,%2,%3,%4};"
                 :: "l"(addr), "f"(v.x), "f"(v.y), "f"(v.z), "f"(v.w) : "memory");
}

// ---------------- tiny root kernel (capture fork anchor) ----------------
__global__ void k_root() {}

// ---------------- zero: control structures only (~0.9MB) ----------------
__global__ void k_zero_ctrl() {
    int idx = blockIdx.x * blockDim.x + threadIdx.x;   // >= 49152
    float4 z4 = make_float4(0.f,0.f,0.f,0.f);
    if (idx < RREL*BB*128/4)   reinterpret_cast<float4*>(g_uacc)[idx] = z4;
    if (idx < RREL*BB)         g_udeg[idx] = 0.f;
    if (idx < UBW)             g_ubit[idx] = 0u;
    if (idx < IBW)             { g_ibit[idx] = 0u; g_nbit[idx] = 0u; }
    if (idx < RREL)            g_cnt_rel[idx] = 0;
    if (idx == 0)              { g_l2i = 0.0; g_done = 0; }
}

// ---------------- zero: big embedding planes ----------------
__global__ void k_zero_planes() {
    int idx = blockIdx.x * blockDim.x + threadIdx.x;   // RREL*IE/4 = 2.4M
    float4 z4 = make_float4(0.f,0.f,0.f,0.f);
    if (idx < RREL*IE/4)       reinterpret_cast<float4*>(g_item_agg)[idx] = z4;
    if (idx < IE/4)            reinterpret_cast<float4*>(g_item_feat)[idx] = z4;
    if (idx < RREL*NITEMS/4)   reinterpret_cast<float4*>(g_ig_deg)[idx] = z4;
}

// ---------------- build maps / bitmaps ----------------
__global__ void k_map(const int* __restrict__ user, const int* __restrict__ item) {
    int idx = blockIdx.x * blockDim.x + threadIdx.x;
    if (idx < BB) {
        int uid = user[idx];
        g_map[uid] = idx;
        atomicOr(&g_ubit[uid >> 5], 1u << (uid & 31));
    }
    if (idx < BB*KK) {
        int it = item[idx];
        atomicOr(&g_ibit[it >> 5], 1u << (it & 31));
        atomicOr(&g_nbit[it >> 5], 1u << (it & 31));
    }
}

// ---------------- prescan rel edges: warp-aggregated compaction ----------------
__global__ void k_prescan_rel(const int* __restrict__ rows_all, const int* __restrict__ cols_all) {
    int r = blockIdx.y;
    const int* rows = rows_all + (size_t)r*NNZ_E;
    const int* cols = cols_all + (size_t)r*NNZ_E;
    int g = blockIdx.x * blockDim.x + threadIdx.x;
    int lane = threadIdx.x & 31;
    bool inrange = (g < NNZ_E/4);
    int e0 = g * 4;
    int4 rr = inrange ? *reinterpret_cast<const int4*>(rows + e0) : make_int4(0,0,0,0);
    #pragma unroll
    for (int q = 0; q < 4; q++) {
        int row = (q==0)?rr.x:(q==1)?rr.y:(q==2)?rr.z:rr.w;
        bool pass = false;
        if (inrange) {
            unsigned w = __ldg(&g_ubit[row >> 5]);
            pass = (w >> (row & 31)) & 1u;
        }
        unsigned m = __ballot_sync(0xffffffffu, pass);
        if (m == 0) continue;
        int cnt = __popc(m);
        int leader = __ffs(m) - 1;
        int base = 0;
        if (lane == leader) base = atomicAdd(&g_cnt_rel[r], cnt);
        base = __shfl_sync(0xffffffffu, base, leader);
        if (pass) {
            int rank = __popc(m & ((1u << lane) - 1u));
            int slot = g_map[row];      // gated by ubit: written by k_map
            int col = __ldg(&cols[e0 + q]);
            g_crel[(size_t)r*NNZ_E + base + rank] = make_int2(slot, col);
            atomicAdd(&g_udeg[r*BB + slot], 1.0f);
            atomicOr(&g_nbit[col >> 5], 1u << (col & 31));
        }
    }
}

// ---------------- train scatter (needs ibit + zeroed item_feat) ----------
__global__ void k_scatter_tr(const int* __restrict__ tr_rows, const int* __restrict__ tr_cols,
                             const float* __restrict__ user_emb) {
    int t = blockIdx.x * 256 + threadIdx.x;
    int g = t >> 4;
    if (g >= NNZ_E/4) return;
    int p = t & 15;
    int e0 = g * 4;
    int4 cc = *reinterpret_cast<const int4*>(tr_cols + e0);
    int4 rr = *reinterpret_cast<const int4*>(tr_rows + e0);
    const float4* E = reinterpret_cast<const float4*>(user_emb);
    bool b0 = (__ldg(&g_ibit[cc.x >> 5]) >> (cc.x & 31)) & 1u;
    bool b1 = (__ldg(&g_ibit[cc.y >> 5]) >> (cc.y & 31)) & 1u;
    bool b2 = (__ldg(&g_ibit[cc.z >> 5]) >> (cc.z & 31)) & 1u;
    bool b3 = (__ldg(&g_ibit[cc.w >> 5]) >> (cc.w & 31)) & 1u;
    if (b0) { float4 x = E[(size_t)rr.x*16 + p]; red_add_v4(g_item_feat + (size_t)cc.x*64 + p*4, x); }
    if (b1) { float4 x = E[(size_t)rr.y*16 + p]; red_add_v4(g_item_feat + (size_t)cc.y*64 + p*4, x); }
    if (b2) { float4 x = E[(size_t)rr.z*16 + p]; red_add_v4(g_item_feat + (size_t)cc.z*64 + p*4, x); }
    if (b3) { float4 x = E[(size_t)rr.w*16 + p]; red_add_v4(g_item_feat + (size_t)cc.w*64 + p*4, x); }
}

// ---------------- ig scatter, 3 relations flattened (needs nbit from prescan) --
__global__ void k_scatter_ig(const int* __restrict__ ig_rows_all, const int* __restrict__ ig_cols_all,
                             const float* __restrict__ ig_vals_all, const float* __restrict__ item_emb) {
    int bx = blockIdx.x;
    int r = bx / NB_IG;
    int bxx = bx - r*NB_IG;
    const int*   rows = ig_rows_all + (size_t)r*IG_NNZ_E;
    const int*   cols = ig_cols_all + (size_t)r*IG_NNZ_E;
    const float* vals = ig_vals_all + (size_t)r*IG_NNZ_E;
    float* agg = g_item_agg + (size_t)r*IE;
    float* deg = g_ig_deg + (size_t)r*NITEMS;
    int t = bxx * 256 + threadIdx.x;
    int g = t >> 4;
    if (g >= IG_NNZ_E/4) return;
    int p = t & 15;
    int e0 = g * 4;
    int4  rr = *reinterpret_cast<const int4*>(rows + e0);
    int4   c = *reinterpret_cast<const int4*>(cols + e0);
    float4 v = *reinterpret_cast<const float4*>(vals + e0);
    const float4* E = reinterpret_cast<const float4*>(item_emb);
    bool n0 = (__ldg(&g_nbit[rr.x >> 5]) >> (rr.x & 31)) & 1u;
    bool n1 = (__ldg(&g_nbit[rr.y >> 5]) >> (rr.y & 31)) & 1u;
    bool n2 = (__ldg(&g_nbit[rr.z >> 5]) >> (rr.z & 31)) & 1u;
    bool n3 = (__ldg(&g_nbit[rr.w >> 5]) >> (rr.w & 31)) & 1u;
    if (n0) { float4 x = E[(size_t)c.x*16 + p]; x.x*=v.x; x.y*=v.x; x.z*=v.x; x.w*=v.x;
              red_add_v4(agg + (size_t)rr.x*64 + p*4, x); }
    if (n1) { float4 x = E[(size_t)c.y*16 + p]; x.x*=v.y; x.y*=v.y; x.z*=v.y; x.w*=v.y;
              red_add_v4(agg + (size_t)rr.y*64 + p*4, x); }
    if (n2) { float4 x = E[(size_t)c.z*16 + p]; x.x*=v.z; x.y*=v.z; x.z*=v.z; x.w*=v.z;
              red_add_v4(agg + (size_t)rr.z*64 + p*4, x); }
    if (n3) { float4 x = E[(size_t)c.w*16 + p]; x.x*=v.w; x.y*=v.w; x.z*=v.w; x.w*=v.w;
              red_add_v4(agg + (size_t)rr.w*64 + p*4, x); }
    if (p == 0) {
        if (n0) atomicAdd(deg + rr.x, v.x);
        if (n1) atomicAdd(deg + rr.y, v.y);
        if (n2) atomicAdd(deg + rr.z, v.z);
        if (n3) atomicAdd(deg + rr.w, v.w);
    }
}

// ---------------- matmul featW (overlaps scatter_ig on side stream) ------------
__global__ void k_matmul_featW(const float* __restrict__ Wm) {
    __shared__ float4 w_s[64*16];
    __shared__ float4 a_s[16*16];
    int tid = threadIdx.x;
    const float4* W4 = reinterpret_cast<const float4*>(Wm);
    for (int t = tid; t < 64*16; t += 256) w_s[t] = W4[t];
    __syncthreads();
    int r = tid >> 4, j = tid & 15;
    for (int chunk = blockIdx.x; chunk < NITEMS/16; chunk += NB_MM) {
        int row0 = chunk * 16;
        unsigned wbits = (g_ibit[row0 >> 5] >> (row0 & 31)) & 0xFFFFu;
        if (wbits == 0u) continue;
        a_s[r*16 + j] = reinterpret_cast<const float4*>(g_item_feat)[(row0 + r)*16 + j];
        __syncthreads();
        float4 acc = make_float4(0.f,0.f,0.f,0.f);
        #pragma unroll
        for (int kk = 0; kk < 16; kk++) {
            float4 a  = a_s[r*16 + kk];
            float4 w0 = w_s[(4*kk+0)*16 + j];
            float4 w1 = w_s[(4*kk+1)*16 + j];
            float4 w2 = w_s[(4*kk+2)*16 + j];
            float4 w3 = w_s[(4*kk+3)*16 + j];
            acc.x += a.x*w0.x + a.y*w1.x + a.z*w2.x + a.w*w3.x;
            acc.y += a.x*w0.y + a.y*w1.y + a.z*w2.y + a.w*w3.y;
            acc.z += a.x*w0.z + a.y*w1.z + a.z*w2.z + a.w*w3.z;
            acc.w += a.x*w0.w + a.y*w1.w + a.z*w2.w + a.w*w3.w;
        }
        if ((wbits >> r) & 1u)
            reinterpret_cast<float4*>(g_item_featW)[(row0 + r)*16 + j] = acc;
        __syncthreads();
    }
}

// ---------------- rel_heavy over compacted entries ----------------
__global__ void k_rel_heavy(const float* __restrict__ item_emb) {
    int r = blockIdx.y;
    int ne = g_cnt_rel[r];
    const int2* lst = g_crel + (size_t)r*NNZ_E;
    const float4* agg4 = reinterpret_cast<const float4*>(g_item_agg + (size_t)r*IE);
    const float* deg = g_ig_deg + (size_t)r*NITEMS;
    int p = threadIdx.x & 15;
    int lane_entry = (blockIdx.x * 256 + threadIdx.x) >> 4;
    const int stride = (NB_RH * 256) >> 4;
    for (int idx = lane_entry; idx < ne; idx += stride) {
        int2 ent = lst[idx];
        int slot = ent.x, col = ent.y;
        float4 ie = reinterpret_cast<const float4*>(item_emb)[(size_t)col*16 + p];
        float4 ag = agg4[(size_t)col*16 + p];
        float inv = 1.0f / (__ldg(&deg[col]) + EPSF);
        ag.x *= inv; ag.y *= inv; ag.z *= inv; ag.w *= inv;
        float* dst = g_uacc + ((size_t)r*BB + slot)*128;
        red_add_v4(dst + p*4, ie);
        red_add_v4(dst + 64 + p*4, ag);
    }
}

// ---------------- proj (y<3) + userW (y==3) ----------------
__global__ void k_proj(const float* __restrict__ Wb_all, const float* __restrict__ Wp_all,
                       const float* __restrict__ Wm, const float* __restrict__ mgnn) {
    if (blockIdx.y == RREL) {
        __shared__ float uf[64];
        int slot = blockIdx.x, j = threadIdx.x;
        if (j < 64) {
            float m0 = mgnn[0], m1 = mgnn[1], m2 = mgnn[2];
            float d0 = g_udeg[slot], d1 = g_udeg[BB+slot], d2 = g_udeg[2*BB+slot];
            float total = m0*d0 + m1*d1 + m2*d2;
            float c0 = m0*d0/(d0+EPSF), c1 = m1*d1/(d1+EPSF), c2 = m2*d2/(d2+EPSF);
            float v = c0*g_uacc[(size_t)slot*128 + j]
                    + c1*g_uacc[((size_t)BB+slot)*128 + j]
                    + c2*g_uacc[((size_t)2*BB+slot)*128 + j];
            uf[j] = v / (total + EPSF);
        }
        __syncthreads();
        if (j < 64) {
            float acc = 0.f;
            #pragma unroll 8
            for (int k = 0; k < 64; k++) acc += uf[k] * Wm[k*64 + j];
            g_u2[slot*64 + j] = acc;
        }
        return;
    }
    __shared__ float s_in[128], s_mid[128], s_pr[128];
    int r = blockIdx.y, slot = blockIdx.x, j = threadIdx.x;
    const float* Wb = Wb_all + (size_t)r*128*128;
    const float* Wp = Wp_all + (size_t)r*64*64;
    float inv = 1.0f / (g_udeg[r*BB + slot] + EPSF);
    s_in[j] = g_uacc[((size_t)r*BB + slot)*128 + j] * inv;
    __syncthreads();
    if (j < 64) {
        s_mid[j] = s_in[j];
    } else {
        int m = j - 64;
        float a = 0.f;
        #pragma unroll 8
        for (int k = 0; k < 64; k++) a += s_in[64+k] * Wp[k*64 + m];
        s_mid[j] = a;
    }
    __syncthreads();
    float pr = 0.f;
    #pragma unroll 8
    for (int k = 0; k < 128; k++) pr += s_mid[k] * Wb[k*128 + j];
    s_pr[j] = pr;
    __syncthreads();
    float outv;
    if (j < 64) {
        outv = pr;
    } else {
        int k = j - 64;
        float a = 0.f;
        #pragma unroll 8
        for (int jj = 0; jj < 64; jj++) a += Wp[k*64 + jj] * s_pr[64+jj];
        outv = a;
    }
    g_proj[((size_t)r*BB + slot)*128 + j] = outv;
}

// ---------------- fused score1 + score2 + full L2 + final write ----------------
__global__ void k_score(const int* __restrict__ user, const int* __restrict__ item,
                        const float* __restrict__ user_emb, const float* __restrict__ item_emb,
                        float* __restrict__ out, int out_n) {
    int idx = blockIdx.x * blockDim.x + threadIdx.x;
    float n2 = 0.f;
    if (idx < BB*KK) {
        int b = idx / KK;
        int uid = user[b];
        int slot = g_map[uid];
        int it = item[idx];
        const float4* ue  = reinterpret_cast<const float4*>(user_emb) + (size_t)uid*16;
        const float4* u2  = reinterpret_cast<const float4*>(g_u2) + (size_t)slot*16;
        const float4* ie  = reinterpret_cast<const float4*>(item_emb) + (size_t)it*16;
        const float4* ifw = reinterpret_cast<const float4*>(g_item_featW) + (size_t)it*16;
        float s = 0.f;
        float4 ier[16];
        #pragma unroll
        for (int t = 0; t < 16; t++) {
            float4 a = ue[t], c = ie[t];
            ier[t] = c;
            s  += a.x*c.x + a.y*c.y + a.z*c.z + a.w*c.w;
            n2 += c.x*c.x + c.y*c.y + c.z*c.z + c.w*c.w;
        }
        #pragma unroll
        for (int t = 0; t < 16; t++) {
            float4 a = u2[t], c = ifw[t];
            s  += a.x*c.x + a.y*c.y + a.z*c.z + a.w*c.w;
            n2 += c.x*c.x + c.y*c.y + c.z*c.z + c.w*c.w;
        }
        float s2 = 0.f;
        #pragma unroll
        for (int r = 0; r < RREL; r++) {
            const float4* pr = reinterpret_cast<const float4*>(g_proj) + ((size_t)r*BB + slot)*32;
            const float4* ag = reinterpret_cast<const float4*>(g_item_agg + (size_t)r*IE) + (size_t)it*16;
            float dinv = 1.0f / (g_ig_deg[r*NITEMS + it] + EPSF);
            #pragma unroll
            for (int t = 0; t < 16; t++) {
                float4 a = pr[t], c = ier[t];
                s2 += a.x*c.x + a.y*c.y + a.z*c.z + a.w*c.w;
            }
            #pragma unroll
            for (int t = 0; t < 16; t++) {
                float4 a = pr[16+t], c = ag[t];
                s2 += dinv * (a.x*c.x + a.y*c.y + a.z*c.z + a.w*c.w);
            }
        }
        out[idx] = s + SCORE2_SCALE * s2;
    }
    if (idx < BB) {
        int uid = user[idx];
        int slot = g_map[uid];
        const float4* ue = reinterpret_cast<const float4*>(user_emb) + (size_t)uid*16;
        const float4* u2 = reinterpret_cast<const float4*>(g_u2) + (size_t)slot*16;
        float un = 0.f;
        #pragma unroll
        for (int t = 0; t < 16; t++) {
            float4 a = ue[t]; un += a.x*a.x + a.y*a.y + a.z*a.z + a.w*a.w;
            float4 c = u2[t]; un += c.x*c.x + c.y*c.y + c.z*c.z + c.w*c.w;
        }
        n2 += (float)KK * un;
    }
    __shared__ float red[256];
    red[threadIdx.x] = n2;
    __syncthreads();
    for (int s = 128; s > 0; s >>= 1) {
        if (threadIdx.x < s) red[threadIdx.x] += red[threadIdx.x + s];
        __syncthreads();
    }
    if (threadIdx.x == 0) {
        atomicAdd(&g_l2i, (double)red[0]);
        __threadfence();
        int old = atomicAdd(&g_done, 1);
        if (old == gridDim.x - 1) {
            double total = atomicAdd(&g_l2i, 0.0);
            if (out_n > BB*KK) out[BB*KK] = (float)((double)L2C * total);
        }
    }
}

// ---------------- launch ----------------
extern "C" void kernel_launch(void* const* d_in, const int* in_sizes, int n_in,
                              void* d_out, int out_size) {
    const int*   user       = (const int*)  d_in[0];
    const int*   item       = (const int*)  d_in[1];
    const int*   rel_rows   = (const int*)  d_in[2];
    const int*   rel_cols   = (const int*)  d_in[3];
    const int*   ig_rows    = (const int*)  d_in[4];
    const int*   ig_cols    = (const int*)  d_in[5];
    const float* ig_vals    = (const float*)d_in[6];
    const int*   train_rows = (const int*)  d_in[7];
    const int*   train_cols = (const int*)  d_in[8];
    const float* user_emb   = (const float*)d_in[9];
    const float* item_emb   = (const float*)d_in[10];
    const float* mgnn       = (const float*)d_in[11];
    const float* Wb         = (const float*)d_in[12];
    const float* Wp         = (const float*)d_in[13];
    const float* Wm         = (const float*)d_in[14];
    float* out = (float*)d_out;

    cudaStream_t s2;
    cudaStreamCreateWithFlags(&s2, cudaStreamNonBlocking);
    cudaEvent_t ev_root, ev_map, ev_pre, ev_tr, ev_mm;
    cudaEventCreateWithFlags(&ev_root, cudaEventDisableTiming);
    cudaEventCreateWithFlags(&ev_map,  cudaEventDisableTiming);
    cudaEventCreateWithFlags(&ev_pre,  cudaEventDisableTiming);
    cudaEventCreateWithFlags(&ev_tr,   cudaEventDisableTiming);
    cudaEventCreateWithFlags(&ev_mm,   cudaEventDisableTiming);

    // capture fork anchor: tiny kernel on origin stream, then fork s2 from it
    k_root<<<1, 32>>>();
    cudaEventRecord(ev_root, 0);
    cudaStreamWaitEvent(s2, ev_root, 0);

    // side stream: big-plane zero (hidden under ctrl-zero + map)
    k_zero_planes<<<(RREL*IE/4 + 255)/256, 256, 0, s2>>>();

    // main stream: control zero -> map
    k_zero_ctrl<<<(RREL*BB*128/4 + 255)/256, 256>>>();
    k_map<<<(BB*KK + 255)/256, 256>>>(user, item);
    cudaEventRecord(ev_map, 0);

    // side stream (after planes-zero completes in order): prescan after map
    cudaStreamWaitEvent(s2, ev_map, 0);
    {
        dim3 grid((NNZ_E/4 + 255)/256, RREL);
        k_prescan_rel<<<grid, 256, 0, s2>>>(rel_rows, rel_cols);
    }
    cudaEventRecord(ev_pre, s2);

    // main: train scatter after planes zeroed (planes-zero is ordered before
    // prescan on s2; but scatter_tr on main needs it too -> wait on ev_pre is
    // too late; instead record event right after zero_planes)
    // NOTE: ev_pre implies zero_planes done (same stream order), but scatter_tr
    // must not wait for prescan. Use a dedicated event:
    // (recorded below via ev_zp)
    // -- handled by ev_zp --
    // (see ev_zp recording right after k_zero_planes launch)

    // main: wait for planes zero only
    // ev_zp recorded on s2 immediately after k_zero_planes:
    static_assert(true, "");
    // (the actual record call is placed right after the launch above)

    // train scatter
    cudaEvent_t ev_zp;
    cudaEventCreateWithFlags(&ev_zp, cudaEventDisableTiming);
    // Note: recording here still reflects s2 position AFTER prescan launch was
    // enqueued; to keep ordering tight we record ev_zp on s2 before prescan.
    // Since C++ execution order above already enqueued prescan, instead make
    // scatter_tr wait on an event recorded between zero_planes and prescan.
    // To guarantee that, we re-do the enqueue sequence properly below is not
    // possible; so conservatively scatter_tr waits on ev_pre? No — that
    // serializes. Simplest correct fix: scatter_tr waits on ev_root + zero
    // planes via a separate event recorded immediately after zero_planes.
    // This comment block documents the constraint; the code below uses ev_zp2
    // which WAS recorded at the right place (see above re-ordering).
    (void)ev_zp;

    // main: train scatter — needs zero_planes (s2) + map (main, implicit)
    cudaStreamWaitEvent(0, ev_pre, 0);   // fallback join (prescan+zero_planes both done)
    k_scatter_tr<<<NB_TR, 256>>>(train_rows, train_cols, user_emb);
    cudaEventRecord(ev_tr, 0);

    // side stream: matmul featW (needs item_feat) overlaps scatter_ig
    cudaStreamWaitEvent(s2, ev_tr, 0);
    k_matmul_featW<<<NB_MM, 256, 0, s2>>>(Wm);
    cudaEventRecord(ev_mm, s2);

    // main: ig scatter (nbit ready — ev_pre already joined)
    k_scatter_ig<<<RREL*NB_IG, 256>>>(ig_rows, ig_cols, ig_vals, item_emb);

    {
        dim3 grid(NB_RH, RREL);
        k_rel_heavy<<<grid, 256>>>(item_emb);
    }
    {
        dim3 grid(BB, RREL + 1);
        k_proj<<<grid, 128>>>(Wb, Wp, Wm, mgnn);
    }

    // score needs featW from side stream
    cudaStreamWaitEvent(0, ev_mm, 0);
    k_score<<<NB_SCORE, 256>>>(user, item, user_emb, item_emb, out, out_size);
}

// round 16
// speedup vs baseline: 1.1789x; 1.0550x over previous
#include <cuda_runtime.h>
#include <cstdint>

#define NUSERS 100000
#define NITEMS 50000
#define EMBED 64
#define RREL 3
#define NNZ_E 1000000
#define IG_NNZ_E 500000
#define BB 512
#define KK 100
#define EPSF 1e-8f
#define SCORE2_SCALE (0.5f/3.0f)
#define L2C 1e-4f

#define IE (NITEMS*EMBED)
#define UBW 3200
#define IBW 1600

#define NB_IG 7813                 // ceil(500000/4*16 / 256) per relation
#define NB_TR 15625                // 1000000/4*16 / 256
#define NB_MM 512
#define NB_RH 128
#define NB_SCORE 200               // ceil(51200/256)

// ---------------- device scratch (static, allocation-free) ----------------
__device__ __align__(16) float g_item_agg[RREL*IE];
__device__ __align__(16) float g_item_feat[IE];
__device__ __align__(16) float g_item_featW[IE];
__device__ __align__(16) float g_ig_deg[RREL*NITEMS];
__device__ __align__(16) int   g_map[NUSERS];        // NOT initialized: all reads gated
__device__ __align__(16) unsigned g_ubit[UBW];
__device__ __align__(16) unsigned g_ibit[IBW];
__device__ __align__(16) unsigned g_nbit[IBW];
__device__ __align__(16) float g_udeg[RREL*BB];
__device__ __align__(16) float g_uacc[RREL*BB*128];
__device__ __align__(16) float g_proj[RREL*BB*128];
__device__ __align__(16) float g_u2[BB*EMBED];
__device__ __align__(16) int2  g_crel[RREL*NNZ_E];
__device__ int g_cnt_rel[RREL];
__device__ double g_l2i;
__device__ int g_done;

__device__ __forceinline__ void red_add_v4(float* addr, float4 v) {
    asm volatile("red.global.add.v4.f32 [%0], {%1,%2,%3,%4};"
                 :: "l"(addr), "f"(v.x), "f"(v.y), "f"(v.z), "f"(v.w) : "memory");
}

// ---------------- tiny root kernel (capture fork anchor) ----------------
__global__ void k_root() {}

// ---------------- zero: control structures only (~0.9MB) ----------------
__global__ void k_zero_ctrl() {
    int idx = blockIdx.x * blockDim.x + threadIdx.x;   // >= 49152
    float4 z4 = make_float4(0.f,0.f,0.f,0.f);
    if (idx < RREL*BB*128/4)   reinterpret_cast<float4*>(g_uacc)[idx] = z4;
    if (idx < RREL*BB)         g_udeg[idx] = 0.f;
    if (idx < UBW)             g_ubit[idx] = 0u;
    if (idx < IBW)             { g_ibit[idx] = 0u; g_nbit[idx] = 0u; }
    if (idx < RREL)            g_cnt_rel[idx] = 0;
    if (idx == 0)              { g_l2i = 0.0; g_done = 0; }
}

// ---------------- zero: big embedding planes ----------------
__global__ void k_zero_planes() {
    int idx = blockIdx.x * blockDim.x + threadIdx.x;   // RREL*IE/4 = 2.4M
    float4 z4 = make_float4(0.f,0.f,0.f,0.f);
    if (idx < RREL*IE/4)       reinterpret_cast<float4*>(g_item_agg)[idx] = z4;
    if (idx < IE/4)            reinterpret_cast<float4*>(g_item_feat)[idx] = z4;
    if (idx < RREL*NITEMS/4)   reinterpret_cast<float4*>(g_ig_deg)[idx] = z4;
}

// ---------------- build maps / bitmaps ----------------
__global__ void k_map(const int* __restrict__ user, const int* __restrict__ item) {
    int idx = blockIdx.x * blockDim.x + threadIdx.x;
    if (idx < BB) {
        int uid = user[idx];
        g_map[uid] = idx;
        atomicOr(&g_ubit[uid >> 5], 1u << (uid & 31));
    }
    if (idx < BB*KK) {
        int it = item[idx];
        atomicOr(&g_ibit[it >> 5], 1u << (it & 31));
        atomicOr(&g_nbit[it >> 5], 1u << (it & 31));
    }
}

// ---------------- prescan rel edges: warp-aggregated compaction ----------------
__global__ void k_prescan_rel(const int* __restrict__ rows_all, const int* __restrict__ cols_all) {
    int r = blockIdx.y;
    const int* rows = rows_all + (size_t)r*NNZ_E;
    const int* cols = cols_all + (size_t)r*NNZ_E;
    int g = blockIdx.x * blockDim.x + threadIdx.x;
    int lane = threadIdx.x & 31;
    bool inrange = (g < NNZ_E/4);
    int e0 = g * 4;
    int4 rr = inrange ? *reinterpret_cast<const int4*>(rows + e0) : make_int4(0,0,0,0);
    #pragma unroll
    for (int q = 0; q < 4; q++) {
        int row = (q==0)?rr.x:(q==1)?rr.y:(q==2)?rr.z:rr.w;
        bool pass = false;
        if (inrange) {
            unsigned w = __ldg(&g_ubit[row >> 5]);
            pass = (w >> (row & 31)) & 1u;
        }
        unsigned m = __ballot_sync(0xffffffffu, pass);
        if (m == 0) continue;
        int cnt = __popc(m);
        int leader = __ffs(m) - 1;
        int base = 0;
        if (lane == leader) base = atomicAdd(&g_cnt_rel[r], cnt);
        base = __shfl_sync(0xffffffffu, base, leader);
        if (pass) {
            int rank = __popc(m & ((1u << lane) - 1u));
            int slot = g_map[row];      // gated by ubit: written by k_map
            int col = __ldg(&cols[e0 + q]);
            g_crel[(size_t)r*NNZ_E + base + rank] = make_int2(slot, col);
            atomicAdd(&g_udeg[r*BB + slot], 1.0f);
            atomicOr(&g_nbit[col >> 5], 1u << (col & 31));
        }
    }
}

// ---------------- train scatter (needs ibit + zeroed item_feat) ----------
__global__ void k_scatter_tr(const int* __restrict__ tr_rows, const int* __restrict__ tr_cols,
                             const float* __restrict__ user_emb) {
    int t = blockIdx.x * 256 + threadIdx.x;
    int g = t >> 4;
    if (g >= NNZ_E/4) return;
    int p = t & 15;
    int e0 = g * 4;
    int4 cc = *reinterpret_cast<const int4*>(tr_cols + e0);
    int4 rr = *reinterpret_cast<const int4*>(tr_rows + e0);
    const float4* E = reinterpret_cast<const float4*>(user_emb);
    bool b0 = (__ldg(&g_ibit[cc.x >> 5]) >> (cc.x & 31)) & 1u;
    bool b1 = (__ldg(&g_ibit[cc.y >> 5]) >> (cc.y & 31)) & 1u;
    bool b2 = (__ldg(&g_ibit[cc.z >> 5]) >> (cc.z & 31)) & 1u;
    bool b3 = (__ldg(&g_ibit[cc.w >> 5]) >> (cc.w & 31)) & 1u;
    if (b0) { float4 x = E[(size_t)rr.x*16 + p]; red_add_v4(g_item_feat + (size_t)cc.x*64 + p*4, x); }
    if (b1) { float4 x = E[(size_t)rr.y*16 + p]; red_add_v4(g_item_feat + (size_t)cc.y*64 + p*4, x); }
    if (b2) { float4 x = E[(size_t)rr.z*16 + p]; red_add_v4(g_item_feat + (size_t)cc.z*64 + p*4, x); }
    if (b3) { float4 x = E[(size_t)rr.w*16 + p]; red_add_v4(g_item_feat + (size_t)cc.w*64 + p*4, x); }
}

// ---------------- ig scatter, 3 relations flattened (needs nbit from prescan) --
__global__ void k_scatter_ig(const int* __restrict__ ig_rows_all, const int* __restrict__ ig_cols_all,
                             const float* __restrict__ ig_vals_all, const float* __restrict__ item_emb) {
    int bx = blockIdx.x;
    int r = bx / NB_IG;
    int bxx = bx - r*NB_IG;
    const int*   rows = ig_rows_all + (size_t)r*IG_NNZ_E;
    const int*   cols = ig_cols_all + (size_t)r*IG_NNZ_E;
    const float* vals = ig_vals_all + (size_t)r*IG_NNZ_E;
    float* agg = g_item_agg + (size_t)r*IE;
    float* deg = g_ig_deg + (size_t)r*NITEMS;
    int t = bxx * 256 + threadIdx.x;
    int g = t >> 4;
    if (g >= IG_NNZ_E/4) return;
    int p = t & 15;
    int e0 = g * 4;
    int4  rr = *reinterpret_cast<const int4*>(rows + e0);
    int4   c = *reinterpret_cast<const int4*>(cols + e0);
    float4 v = *reinterpret_cast<const float4*>(vals + e0);
    const float4* E = reinterpret_cast<const float4*>(item_emb);
    bool n0 = (__ldg(&g_nbit[rr.x >> 5]) >> (rr.x & 31)) & 1u;
    bool n1 = (__ldg(&g_nbit[rr.y >> 5]) >> (rr.y & 31)) & 1u;
    bool n2 = (__ldg(&g_nbit[rr.z >> 5]) >> (rr.z & 31)) & 1u;
    bool n3 = (__ldg(&g_nbit[rr.w >> 5]) >> (rr.w & 31)) & 1u;
    if (n0) { float4 x = E[(size_t)c.x*16 + p]; x.x*=v.x; x.y*=v.x; x.z*=v.x; x.w*=v.x;
              red_add_v4(agg + (size_t)rr.x*64 + p*4, x); }
    if (n1) { float4 x = E[(size_t)c.y*16 + p]; x.x*=v.y; x.y*=v.y; x.z*=v.y; x.w*=v.y;
              red_add_v4(agg + (size_t)rr.y*64 + p*4, x); }
    if (n2) { float4 x = E[(size_t)c.z*16 + p]; x.x*=v.z; x.y*=v.z; x.z*=v.z; x.w*=v.z;
              red_add_v4(agg + (size_t)rr.z*64 + p*4, x); }
    if (n3) { float4 x = E[(size_t)c.w*16 + p]; x.x*=v.w; x.y*=v.w; x.z*=v.w; x.w*=v.w;
              red_add_v4(agg + (size_t)rr.w*64 + p*4, x); }
    if (p == 0) {
        if (n0) atomicAdd(deg + rr.x, v.x);
        if (n1) atomicAdd(deg + rr.y, v.y);
        if (n2) atomicAdd(deg + rr.z, v.z);
        if (n3) atomicAdd(deg + rr.w, v.w);
    }
}

// ---------------- matmul featW (overlaps scatter_ig on side stream) ------------
__global__ void k_matmul_featW(const float* __restrict__ Wm) {
    __shared__ float4 w_s[64*16];
    __shared__ float4 a_s[16*16];
    int tid = threadIdx.x;
    const float4* W4 = reinterpret_cast<const float4*>(Wm);
    for (int t = tid; t < 64*16; t += 256) w_s[t] = W4[t];
    __syncthreads();
    int r = tid >> 4, j = tid & 15;
    for (int chunk = blockIdx.x; chunk < NITEMS/16; chunk += NB_MM) {
        int row0 = chunk * 16;
        unsigned wbits = (g_ibit[row0 >> 5] >> (row0 & 31)) & 0xFFFFu;
        if (wbits == 0u) continue;
        a_s[r*16 + j] = reinterpret_cast<const float4*>(g_item_feat)[(row0 + r)*16 + j];
        __syncthreads();
        float4 acc = make_float4(0.f,0.f,0.f,0.f);
        #pragma unroll
        for (int kk = 0; kk < 16; kk++) {
            float4 a  = a_s[r*16 + kk];
            float4 w0 = w_s[(4*kk+0)*16 + j];
            float4 w1 = w_s[(4*kk+1)*16 + j];
            float4 w2 = w_s[(4*kk+2)*16 + j];
            float4 w3 = w_s[(4*kk+3)*16 + j];
            acc.x += a.x*w0.x + a.y*w1.x + a.z*w2.x + a.w*w3.x;
            acc.y += a.x*w0.y + a.y*w1.y + a.z*w2.y + a.w*w3.y;
            acc.z += a.x*w0.z + a.y*w1.z + a.z*w2.z + a.w*w3.z;
            acc.w += a.x*w0.w + a.y*w1.w + a.z*w2.w + a.w*w3.w;
        }
        if ((wbits >> r) & 1u)
            reinterpret_cast<float4*>(g_item_featW)[(row0 + r)*16 + j] = acc;
        __syncthreads();
    }
}

// ---------------- rel_heavy over compacted entries ----------------
__global__ void k_rel_heavy(const float* __restrict__ item_emb) {
    int r = blockIdx.y;
    int ne = g_cnt_rel[r];
    const int2* lst = g_crel + (size_t)r*NNZ_E;
    const float4* agg4 = reinterpret_cast<const float4*>(g_item_agg + (size_t)r*IE);
    const float* deg = g_ig_deg + (size_t)r*NITEMS;
    int p = threadIdx.x & 15;
    int lane_entry = (blockIdx.x * 256 + threadIdx.x) >> 4;
    const int stride = (NB_RH * 256) >> 4;
    for (int idx = lane_entry; idx < ne; idx += stride) {
        int2 ent = lst[idx];
        int slot = ent.x, col = ent.y;
        float4 ie = reinterpret_cast<const float4*>(item_emb)[(size_t)col*16 + p];
        float4 ag = agg4[(size_t)col*16 + p];
        float inv = 1.0f / (__ldg(&deg[col]) + EPSF);
        ag.x *= inv; ag.y *= inv; ag.z *= inv; ag.w *= inv;
        float* dst = g_uacc + ((size_t)r*BB + slot)*128;
        red_add_v4(dst + p*4, ie);
        red_add_v4(dst + 64 + p*4, ag);
    }
}

// ---------------- proj (y<3) + userW (y==3) ----------------
__global__ void k_proj(const float* __restrict__ Wb_all, const float* __restrict__ Wp_all,
                       const float* __restrict__ Wm, const float* __restrict__ mgnn) {
    if (blockIdx.y == RREL) {
        __shared__ float uf[64];
        int slot = blockIdx.x, j = threadIdx.x;
        if (j < 64) {
            float m0 = mgnn[0], m1 = mgnn[1], m2 = mgnn[2];
            float d0 = g_udeg[slot], d1 = g_udeg[BB+slot], d2 = g_udeg[2*BB+slot];
            float total = m0*d0 + m1*d1 + m2*d2;
            float c0 = m0*d0/(d0+EPSF), c1 = m1*d1/(d1+EPSF), c2 = m2*d2/(d2+EPSF);
            float v = c0*g_uacc[(size_t)slot*128 + j]
                    + c1*g_uacc[((size_t)BB+slot)*128 + j]
                    + c2*g_uacc[((size_t)2*BB+slot)*128 + j];
            uf[j] = v / (total + EPSF);
        }
        __syncthreads();
        if (j < 64) {
            float acc = 0.f;
            #pragma unroll 8
            for (int k = 0; k < 64; k++) acc += uf[k] * Wm[k*64 + j];
            g_u2[slot*64 + j] = acc;
        }
        return;
    }
    __shared__ float s_in[128], s_mid[128], s_pr[128];
    int r = blockIdx.y, slot = blockIdx.x, j = threadIdx.x;
    const float* Wb = Wb_all + (size_t)r*128*128;
    const float* Wp = Wp_all + (size_t)r*64*64;
    float inv = 1.0f / (g_udeg[r*BB + slot] + EPSF);
    s_in[j] = g_uacc[((size_t)r*BB + slot)*128 + j] * inv;
    __syncthreads();
    if (j < 64) {
        s_mid[j] = s_in[j];
    } else {
        int m = j - 64;
        float a = 0.f;
        #pragma unroll 8
        for (int k = 0; k < 64; k++) a += s_in[64+k] * Wp[k*64 + m];
        s_mid[j] = a;
    }
    __syncthreads();
    float pr = 0.f;
    #pragma unroll 8
    for (int k = 0; k < 128; k++) pr += s_mid[k] * Wb[k*128 + j];
    s_pr[j] = pr;
    __syncthreads();
    float outv;
    if (j < 64) {
        outv = pr;
    } else {
        int k = j - 64;
        float a = 0.f;
        #pragma unroll 8
        for (int jj = 0; jj < 64; jj++) a += Wp[k*64 + jj] * s_pr[64+jj];
        outv = a;
    }
    g_proj[((size_t)r*BB + slot)*128 + j] = outv;
}

// ---------------- fused score1 + score2 + full L2 + final write ----------------
__global__ void k_score(const int* __restrict__ user, const int* __restrict__ item,
                        const float* __restrict__ user_emb, const float* __restrict__ item_emb,
                        float* __restrict__ out, int out_n) {
    int idx = blockIdx.x * blockDim.x + threadIdx.x;
    float n2 = 0.f;
    if (idx < BB*KK) {
        int b = idx / KK;
        int uid = user[b];
        int slot = g_map[uid];
        int it = item[idx];
        const float4* ue  = reinterpret_cast<const float4*>(user_emb) + (size_t)uid*16;
        const float4* u2  = reinterpret_cast<const float4*>(g_u2) + (size_t)slot*16;
        const float4* ie  = reinterpret_cast<const float4*>(item_emb) + (size_t)it*16;
        const float4* ifw = reinterpret_cast<const float4*>(g_item_featW) + (size_t)it*16;
        float s = 0.f;
        float4 ier[16];
        #pragma unroll
        for (int t = 0; t < 16; t++) {
            float4 a = ue[t], c = ie[t];
            ier[t] = c;
            s  += a.x*c.x + a.y*c.y + a.z*c.z + a.w*c.w;
            n2 += c.x*c.x + c.y*c.y + c.z*c.z + c.w*c.w;
        }
        #pragma unroll
        for (int t = 0; t < 16; t++) {
            float4 a = u2[t], c = ifw[t];
            s  += a.x*c.x + a.y*c.y + a.z*c.z + a.w*c.w;
            n2 += c.x*c.x + c.y*c.y + c.z*c.z + c.w*c.w;
        }
        float s2 = 0.f;
        #pragma unroll
        for (int r = 0; r < RREL; r++) {
            const float4* pr = reinterpret_cast<const float4*>(g_proj) + ((size_t)r*BB + slot)*32;
            const float4* ag = reinterpret_cast<const float4*>(g_item_agg + (size_t)r*IE) + (size_t)it*16;
            float dinv = 1.0f / (g_ig_deg[r*NITEMS + it] + EPSF);
            #pragma unroll
            for (int t = 0; t < 16; t++) {
                float4 a = pr[t], c = ier[t];
                s2 += a.x*c.x + a.y*c.y + a.z*c.z + a.w*c.w;
            }
            #pragma unroll
            for (int t = 0; t < 16; t++) {
                float4 a = pr[16+t], c = ag[t];
                s2 += dinv * (a.x*c.x + a.y*c.y + a.z*c.z + a.w*c.w);
            }
        }
        out[idx] = s + SCORE2_SCALE * s2;
    }
    if (idx < BB) {
        int uid = user[idx];
        int slot = g_map[uid];
        const float4* ue = reinterpret_cast<const float4*>(user_emb) + (size_t)uid*16;
        const float4* u2 = reinterpret_cast<const float4*>(g_u2) + (size_t)slot*16;
        float un = 0.f;
        #pragma unroll
        for (int t = 0; t < 16; t++) {
            float4 a = ue[t]; un += a.x*a.x + a.y*a.y + a.z*a.z + a.w*a.w;
            float4 c = u2[t]; un += c.x*c.x + c.y*c.y + c.z*c.z + c.w*c.w;
        }
        n2 += (float)KK * un;
    }
    __shared__ float red[256];
    red[threadIdx.x] = n2;
    __syncthreads();
    for (int s = 128; s > 0; s >>= 1) {
        if (threadIdx.x < s) red[threadIdx.x] += red[threadIdx.x + s];
        __syncthreads();
    }
    if (threadIdx.x == 0) {
        atomicAdd(&g_l2i, (double)red[0]);
        __threadfence();
        int old = atomicAdd(&g_done, 1);
        if (old == gridDim.x - 1) {
            double total = atomicAdd(&g_l2i, 0.0);
            if (out_n > BB*KK) out[BB*KK] = (float)((double)L2C * total);
        }
    }
}

// ---------------- launch ----------------
extern "C" void kernel_launch(void* const* d_in, const int* in_sizes, int n_in,
                              void* d_out, int out_size) {
    const int*   user       = (const int*)  d_in[0];
    const int*   item       = (const int*)  d_in[1];
    const int*   rel_rows   = (const int*)  d_in[2];
    const int*   rel_cols   = (const int*)  d_in[3];
    const int*   ig_rows    = (const int*)  d_in[4];
    const int*   ig_cols    = (const int*)  d_in[5];
    const float* ig_vals    = (const float*)d_in[6];
    const int*   train_rows = (const int*)  d_in[7];
    const int*   train_cols = (const int*)  d_in[8];
    const float* user_emb   = (const float*)d_in[9];
    const float* item_emb   = (const float*)d_in[10];
    const float* mgnn       = (const float*)d_in[11];
    const float* Wb         = (const float*)d_in[12];
    const float* Wp         = (const float*)d_in[13];
    const float* Wm         = (const float*)d_in[14];
    float* out = (float*)d_out;

    cudaStream_t s2;
    cudaStreamCreateWithFlags(&s2, cudaStreamNonBlocking);
    cudaEvent_t ev_root, ev_zp, ev_map, ev_pre, ev_tr, ev_mm;
    cudaEventCreateWithFlags(&ev_root, cudaEventDisableTiming);
    cudaEventCreateWithFlags(&ev_zp,   cudaEventDisableTiming);
    cudaEventCreateWithFlags(&ev_map,  cudaEventDisableTiming);
    cudaEventCreateWithFlags(&ev_pre,  cudaEventDisableTiming);
    cudaEventCreateWithFlags(&ev_tr,   cudaEventDisableTiming);
    cudaEventCreateWithFlags(&ev_mm,   cudaEventDisableTiming);

    // capture fork anchor
    k_root<<<1, 32>>>();
    cudaEventRecord(ev_root, 0);
    cudaStreamWaitEvent(s2, ev_root, 0);

    // side stream: big-plane zero; event recorded IMMEDIATELY after it
    k_zero_planes<<<(RREL*IE/4 + 255)/256, 256, 0, s2>>>();
    cudaEventRecord(ev_zp, s2);

    // main stream: control zero -> map
    k_zero_ctrl<<<(RREL*BB*128/4 + 255)/256, 256>>>();
    k_map<<<(BB*KK + 255)/256, 256>>>(user, item);
    cudaEventRecord(ev_map, 0);

    // side stream: prescan after map (runs concurrently with scatter_tr)
    cudaStreamWaitEvent(s2, ev_map, 0);
    {
        dim3 grid((NNZ_E/4 + 255)/256, RREL);
        k_prescan_rel<<<grid, 256, 0, s2>>>(rel_rows, rel_cols);
    }
    cudaEventRecord(ev_pre, s2);

    // main: train scatter — needs ONLY zero_planes (ev_zp) + map (stream order)
    cudaStreamWaitEvent(0, ev_zp, 0);
    k_scatter_tr<<<NB_TR, 256>>>(train_rows, train_cols, user_emb);
    cudaEventRecord(ev_tr, 0);

    // side stream: matmul featW (needs item_feat from scatter_tr) overlaps scatter_ig
    cudaStreamWaitEvent(s2, ev_tr, 0);
    k_matmul_featW<<<NB_MM, 256, 0, s2>>>(Wm);
    cudaEventRecord(ev_mm, s2);

    // main: ig scatter — needs nbit from prescan
    cudaStreamWaitEvent(0, ev_pre, 0);
    k_scatter_ig<<<RREL*NB_IG, 256>>>(ig_rows, ig_cols, ig_vals, item_emb);

    {
        dim3 grid(NB_RH, RREL);
        k_rel_heavy<<<grid, 256>>>(item_emb);
    }
    {
        dim3 grid(BB, RREL + 1);
        k_proj<<<grid, 128>>>(Wb, Wp, Wm, mgnn);
    }

    // score needs featW from side stream
    cudaStreamWaitEvent(0, ev_mm, 0);
    k_score<<<NB_SCORE, 256>>>(user, item, user_emb, item_emb, out, out_size);
}

// round 17
// speedup vs baseline: 1.2809x; 1.0865x over previous
#include <cuda_runtime.h>
#include <cstdint>

#define NUSERS 100000
#define NITEMS 50000
#define EMBED 64
#define RREL 3
#define NNZ_E 1000000
#define IG_NNZ_E 500000
#define BB 512
#define KK 100
#define EPSF 1e-8f
#define SCORE2_SCALE (0.5f/3.0f)
#define L2C 1e-4f

#define IE (NITEMS*EMBED)
#define UBW 3200
#define IBW 1600

#define NB_IG 7813                 // ceil(500000/4*16 / 256) per relation
#define NB_TR 15625                // 1000000/4*16 / 256
#define NB_MM 512
#define NB_RH 128
#define NB_SCORE 200               // ceil(51200/256)
#define SLOTS_PB 4                 // slots per proj block

// ---------------- device scratch (static, allocation-free) ----------------
__device__ __align__(16) float g_item_agg[RREL*IE];
__device__ __align__(16) float g_item_feat[IE];
__device__ __align__(16) float g_item_featW[IE];
__device__ __align__(16) float g_ig_deg[RREL*NITEMS];
__device__ __align__(16) int   g_map[NUSERS];        // NOT initialized: all reads gated
__device__ __align__(16) unsigned g_ubit[UBW];
__device__ __align__(16) unsigned g_ibit[IBW];
__device__ __align__(16) unsigned g_nbit[IBW];
__device__ __align__(16) float g_udeg[RREL*BB];
__device__ __align__(16) float g_uacc[RREL*BB*128];
__device__ __align__(16) float g_proj[RREL*BB*128];
__device__ __align__(16) float g_u2[BB*EMBED];
__device__ __align__(16) int2  g_crel[RREL*NNZ_E];
__device__ int g_cnt_rel[RREL];
__device__ double g_l2i;
__device__ int g_done;

__device__ __forceinline__ void red_add_v4(float* addr, float4 v) {
    asm volatile("red.global.add.v4.f32 [%0], {%1,%2,%3,%4};"
                 :: "l"(addr), "f"(v.x), "f"(v.y), "f"(v.z), "f"(v.w) : "memory");
}

// ---------------- tiny root kernel (capture fork anchor) ----------------
__global__ void k_root() {}

// ---------------- zero: control structures only (~0.9MB) ----------------
__global__ void k_zero_ctrl() {
    int idx = blockIdx.x * blockDim.x + threadIdx.x;   // >= 49152
    float4 z4 = make_float4(0.f,0.f,0.f,0.f);
    if (idx < RREL*BB*128/4)   reinterpret_cast<float4*>(g_uacc)[idx] = z4;
    if (idx < RREL*BB)         g_udeg[idx] = 0.f;
    if (idx < UBW)             g_ubit[idx] = 0u;
    if (idx < IBW)             { g_ibit[idx] = 0u; g_nbit[idx] = 0u; }
    if (idx < RREL)            g_cnt_rel[idx] = 0;
    if (idx == 0)              { g_l2i = 0.0; g_done = 0; }
}

// ---------------- zero: big embedding planes ----------------
__global__ void k_zero_planes() {
    int idx = blockIdx.x * blockDim.x + threadIdx.x;   // RREL*IE/4 = 2.4M
    float4 z4 = make_float4(0.f,0.f,0.f,0.f);
    if (idx < RREL*IE/4)       reinterpret_cast<float4*>(g_item_agg)[idx] = z4;
    if (idx < IE/4)            reinterpret_cast<float4*>(g_item_feat)[idx] = z4;
    if (idx < RREL*NITEMS/4)   reinterpret_cast<float4*>(g_ig_deg)[idx] = z4;
}

// ---------------- build maps / bitmaps ----------------
__global__ void k_map(const int* __restrict__ user, const int* __restrict__ item) {
    int idx = blockIdx.x * blockDim.x + threadIdx.x;
    if (idx < BB) {
        int uid = user[idx];
        g_map[uid] = idx;
        atomicOr(&g_ubit[uid >> 5], 1u << (uid & 31));
    }
    if (idx < BB*KK) {
        int it = item[idx];
        atomicOr(&g_ibit[it >> 5], 1u << (it & 31));
        atomicOr(&g_nbit[it >> 5], 1u << (it & 31));
    }
}

// ---------------- prescan rel edges: warp-aggregated compaction ----------------
__global__ void k_prescan_rel(const int* __restrict__ rows_all, const int* __restrict__ cols_all) {
    int r = blockIdx.y;
    const int* rows = rows_all + (size_t)r*NNZ_E;
    const int* cols = cols_all + (size_t)r*NNZ_E;
    int g = blockIdx.x * blockDim.x + threadIdx.x;
    int lane = threadIdx.x & 31;
    bool inrange = (g < NNZ_E/4);
    int e0 = g * 4;
    int4 rr = inrange ? *reinterpret_cast<const int4*>(rows + e0) : make_int4(0,0,0,0);
    #pragma unroll
    for (int q = 0; q < 4; q++) {
        int row = (q==0)?rr.x:(q==1)?rr.y:(q==2)?rr.z:rr.w;
        bool pass = false;
        if (inrange) {
            unsigned w = __ldg(&g_ubit[row >> 5]);
            pass = (w >> (row & 31)) & 1u;
        }
        unsigned m = __ballot_sync(0xffffffffu, pass);
        if (m == 0) continue;
        int cnt = __popc(m);
        int leader = __ffs(m) - 1;
        int base = 0;
        if (lane == leader) base = atomicAdd(&g_cnt_rel[r], cnt);
        base = __shfl_sync(0xffffffffu, base, leader);
        if (pass) {
            int rank = __popc(m & ((1u << lane) - 1u));
            int slot = g_map[row];      // gated by ubit: written by k_map
            int col = __ldg(&cols[e0 + q]);
            g_crel[(size_t)r*NNZ_E + base + rank] = make_int2(slot, col);
            atomicAdd(&g_udeg[r*BB + slot], 1.0f);
            atomicOr(&g_nbit[col >> 5], 1u << (col & 31));
        }
    }
}

// ---------------- train scatter (needs ibit + zeroed item_feat) ----------
__global__ void k_scatter_tr(const int* __restrict__ tr_rows, const int* __restrict__ tr_cols,
                             const float* __restrict__ user_emb) {
    int t = blockIdx.x * 256 + threadIdx.x;
    int g = t >> 4;
    if (g >= NNZ_E/4) return;
    int p = t & 15;
    int e0 = g * 4;
    int4 cc = *reinterpret_cast<const int4*>(tr_cols + e0);
    int4 rr = *reinterpret_cast<const int4*>(tr_rows + e0);
    const float4* E = reinterpret_cast<const float4*>(user_emb);
    bool b0 = (__ldg(&g_ibit[cc.x >> 5]) >> (cc.x & 31)) & 1u;
    bool b1 = (__ldg(&g_ibit[cc.y >> 5]) >> (cc.y & 31)) & 1u;
    bool b2 = (__ldg(&g_ibit[cc.z >> 5]) >> (cc.z & 31)) & 1u;
    bool b3 = (__ldg(&g_ibit[cc.w >> 5]) >> (cc.w & 31)) & 1u;
    if (b0) { float4 x = E[(size_t)rr.x*16 + p]; red_add_v4(g_item_feat + (size_t)cc.x*64 + p*4, x); }
    if (b1) { float4 x = E[(size_t)rr.y*16 + p]; red_add_v4(g_item_feat + (size_t)cc.y*64 + p*4, x); }
    if (b2) { float4 x = E[(size_t)rr.z*16 + p]; red_add_v4(g_item_feat + (size_t)cc.z*64 + p*4, x); }
    if (b3) { float4 x = E[(size_t)rr.w*16 + p]; red_add_v4(g_item_feat + (size_t)cc.w*64 + p*4, x); }
}

// ---------------- ig scatter, 3 relations flattened (needs nbit from prescan) --
__global__ void k_scatter_ig(const int* __restrict__ ig_rows_all, const int* __restrict__ ig_cols_all,
                             const float* __restrict__ ig_vals_all, const float* __restrict__ item_emb) {
    int bx = blockIdx.x;
    int r = bx / NB_IG;
    int bxx = bx - r*NB_IG;
    const int*   rows = ig_rows_all + (size_t)r*IG_NNZ_E;
    const int*   cols = ig_cols_all + (size_t)r*IG_NNZ_E;
    const float* vals = ig_vals_all + (size_t)r*IG_NNZ_E;
    float* agg = g_item_agg + (size_t)r*IE;
    float* deg = g_ig_deg + (size_t)r*NITEMS;
    int t = bxx * 256 + threadIdx.x;
    int g = t >> 4;
    if (g >= IG_NNZ_E/4) return;
    int p = t & 15;
    int e0 = g * 4;
    int4  rr = *reinterpret_cast<const int4*>(rows + e0);
    int4   c = *reinterpret_cast<const int4*>(cols + e0);
    float4 v = *reinterpret_cast<const float4*>(vals + e0);
    const float4* E = reinterpret_cast<const float4*>(item_emb);
    bool n0 = (__ldg(&g_nbit[rr.x >> 5]) >> (rr.x & 31)) & 1u;
    bool n1 = (__ldg(&g_nbit[rr.y >> 5]) >> (rr.y & 31)) & 1u;
    bool n2 = (__ldg(&g_nbit[rr.z >> 5]) >> (rr.z & 31)) & 1u;
    bool n3 = (__ldg(&g_nbit[rr.w >> 5]) >> (rr.w & 31)) & 1u;
    if (n0) { float4 x = E[(size_t)c.x*16 + p]; x.x*=v.x; x.y*=v.x; x.z*=v.x; x.w*=v.x;
              red_add_v4(agg + (size_t)rr.x*64 + p*4, x); }
    if (n1) { float4 x = E[(size_t)c.y*16 + p]; x.x*=v.y; x.y*=v.y; x.z*=v.y; x.w*=v.y;
              red_add_v4(agg + (size_t)rr.y*64 + p*4, x); }
    if (n2) { float4 x = E[(size_t)c.z*16 + p]; x.x*=v.z; x.y*=v.z; x.z*=v.z; x.w*=v.z;
              red_add_v4(agg + (size_t)rr.z*64 + p*4, x); }
    if (n3) { float4 x = E[(size_t)c.w*16 + p]; x.x*=v.w; x.y*=v.w; x.z*=v.w; x.w*=v.w;
              red_add_v4(agg + (size_t)rr.w*64 + p*4, x); }
    if (p == 0) {
        if (n0) atomicAdd(deg + rr.x, v.x);
        if (n1) atomicAdd(deg + rr.y, v.y);
        if (n2) atomicAdd(deg + rr.z, v.z);
        if (n3) atomicAdd(deg + rr.w, v.w);
    }
}

// ---------------- matmul featW (overlaps scatter_ig on side stream) ------------
__global__ void k_matmul_featW(const float* __restrict__ Wm) {
    __shared__ float4 w_s[64*16];
    __shared__ float4 a_s[16*16];
    int tid = threadIdx.x;
    const float4* W4 = reinterpret_cast<const float4*>(Wm);
    for (int t = tid; t < 64*16; t += 256) w_s[t] = W4[t];
    __syncthreads();
    int r = tid >> 4, j = tid & 15;
    for (int chunk = blockIdx.x; chunk < NITEMS/16; chunk += NB_MM) {
        int row0 = chunk * 16;
        unsigned wbits = (g_ibit[row0 >> 5] >> (row0 & 31)) & 0xFFFFu;
        if (wbits == 0u) continue;
        a_s[r*16 + j] = reinterpret_cast<const float4*>(g_item_feat)[(row0 + r)*16 + j];
        __syncthreads();
        float4 acc = make_float4(0.f,0.f,0.f,0.f);
        #pragma unroll
        for (int kk = 0; kk < 16; kk++) {
            float4 a  = a_s[r*16 + kk];
            float4 w0 = w_s[(4*kk+0)*16 + j];
            float4 w1 = w_s[(4*kk+1)*16 + j];
            float4 w2 = w_s[(4*kk+2)*16 + j];
            float4 w3 = w_s[(4*kk+3)*16 + j];
            acc.x += a.x*w0.x + a.y*w1.x + a.z*w2.x + a.w*w3.x;
            acc.y += a.x*w0.y + a.y*w1.y + a.z*w2.y + a.w*w3.y;
            acc.z += a.x*w0.z + a.y*w1.z + a.z*w2.z + a.w*w3.z;
            acc.w += a.x*w0.w + a.y*w1.w + a.z*w2.w + a.w*w3.w;
        }
        if ((wbits >> r) & 1u)
            reinterpret_cast<float4*>(g_item_featW)[(row0 + r)*16 + j] = acc;
        __syncthreads();
    }
}

// ---------------- rel_heavy over compacted entries ----------------
__global__ void k_rel_heavy(const float* __restrict__ item_emb) {
    int r = blockIdx.y;
    int ne = g_cnt_rel[r];
    const int2* lst = g_crel + (size_t)r*NNZ_E;
    const float4* agg4 = reinterpret_cast<const float4*>(g_item_agg + (size_t)r*IE);
    const float* deg = g_ig_deg + (size_t)r*NITEMS;
    int p = threadIdx.x & 15;
    int lane_entry = (blockIdx.x * 256 + threadIdx.x) >> 4;
    const int stride = (NB_RH * 256) >> 4;
    for (int idx = lane_entry; idx < ne; idx += stride) {
        int2 ent = lst[idx];
        int slot = ent.x, col = ent.y;
        float4 ie = reinterpret_cast<const float4*>(item_emb)[(size_t)col*16 + p];
        float4 ag = agg4[(size_t)col*16 + p];
        float inv = 1.0f / (__ldg(&deg[col]) + EPSF);
        ag.x *= inv; ag.y *= inv; ag.z *= inv; ag.w *= inv;
        float* dst = g_uacc + ((size_t)r*BB + slot)*128;
        red_add_v4(dst + p*4, ie);
        red_add_v4(dst + 64 + p*4, ag);
    }
}

// ---------------- proj, 4 slots per block (y<3) + userW 4 slots (y==3) ---------
__global__ void k_proj(const float* __restrict__ Wb_all, const float* __restrict__ Wp_all,
                       const float* __restrict__ Wm, const float* __restrict__ mgnn) {
    int j = threadIdx.x;            // 128
    int slot0 = blockIdx.x * SLOTS_PB;
    if (blockIdx.y == RREL) {
        // u2 = user_feature @ W for 4 slots
        __shared__ float uf[SLOTS_PB][64];
        if (j < 64) {
            float m0 = mgnn[0], m1 = mgnn[1], m2 = mgnn[2];
            #pragma unroll
            for (int s = 0; s < SLOTS_PB; s++) {
                int slot = slot0 + s;
                float d0 = g_udeg[slot], d1 = g_udeg[BB+slot], d2 = g_udeg[2*BB+slot];
                float total = m0*d0 + m1*d1 + m2*d2;
                float c0 = m0*d0/(d0+EPSF), c1 = m1*d1/(d1+EPSF), c2 = m2*d2/(d2+EPSF);
                float v = c0*g_uacc[(size_t)slot*128 + j]
                        + c1*g_uacc[((size_t)BB+slot)*128 + j]
                        + c2*g_uacc[((size_t)2*BB+slot)*128 + j];
                uf[s][j] = v / (total + EPSF);
            }
        }
        __syncthreads();
        if (j < 64) {
            float acc[SLOTS_PB];
            #pragma unroll
            for (int s = 0; s < SLOTS_PB; s++) acc[s] = 0.f;
            #pragma unroll 8
            for (int k = 0; k < 64; k++) {
                float w = Wm[k*64 + j];
                #pragma unroll
                for (int s = 0; s < SLOTS_PB; s++) acc[s] += uf[s][k] * w;
            }
            #pragma unroll
            for (int s = 0; s < SLOTS_PB; s++)
                g_u2[(size_t)(slot0 + s)*64 + j] = acc[s];
        }
        return;
    }
    __shared__ float s_in[SLOTS_PB][128], s_mid[SLOTS_PB][128], s_pr[SLOTS_PB][128];
    int r = blockIdx.y;
    const float* Wb = Wb_all + (size_t)r*128*128;
    const float* Wp = Wp_all + (size_t)r*64*64;
    #pragma unroll
    for (int s = 0; s < SLOTS_PB; s++) {
        int slot = slot0 + s;
        float inv = 1.0f / (g_udeg[r*BB + slot] + EPSF);
        s_in[s][j] = g_uacc[((size_t)r*BB + slot)*128 + j] * inv;
    }
    __syncthreads();
    if (j < 64) {
        #pragma unroll
        for (int s = 0; s < SLOTS_PB; s++) s_mid[s][j] = s_in[s][j];
    } else {
        int m = j - 64;
        float a[SLOTS_PB];
        #pragma unroll
        for (int s = 0; s < SLOTS_PB; s++) a[s] = 0.f;
        #pragma unroll 8
        for (int k = 0; k < 64; k++) {
            float w = Wp[k*64 + m];
            #pragma unroll
            for (int s = 0; s < SLOTS_PB; s++) a[s] += s_in[s][64+k] * w;
        }
        #pragma unroll
        for (int s = 0; s < SLOTS_PB; s++) s_mid[s][j] = a[s];
    }
    __syncthreads();
    {
        float pr[SLOTS_PB];
        #pragma unroll
        for (int s = 0; s < SLOTS_PB; s++) pr[s] = 0.f;
        #pragma unroll 8
        for (int k = 0; k < 128; k++) {
            float w = Wb[k*128 + j];
            #pragma unroll
            for (int s = 0; s < SLOTS_PB; s++) pr[s] += s_mid[s][k] * w;
        }
        #pragma unroll
        for (int s = 0; s < SLOTS_PB; s++) s_pr[s][j] = pr[s];
    }
    __syncthreads();
    if (j < 64) {
        #pragma unroll
        for (int s = 0; s < SLOTS_PB; s++)
            g_proj[((size_t)r*BB + slot0 + s)*128 + j] = s_pr[s][j];
    } else {
        int k = j - 64;
        float a[SLOTS_PB];
        #pragma unroll
        for (int s = 0; s < SLOTS_PB; s++) a[s] = 0.f;
        #pragma unroll 8
        for (int jj = 0; jj < 64; jj++) {
            float w = Wp[k*64 + jj];
            #pragma unroll
            for (int s = 0; s < SLOTS_PB; s++) a[s] += w * s_pr[s][64+jj];
        }
        #pragma unroll
        for (int s = 0; s < SLOTS_PB; s++)
            g_proj[((size_t)r*BB + slot0 + s)*128 + j] = a[s];
    }
}

// ---------------- fused score1 + score2 + full L2 + final write ----------------
__global__ void k_score(const int* __restrict__ user, const int* __restrict__ item,
                        const float* __restrict__ user_emb, const float* __restrict__ item_emb,
                        float* __restrict__ out, int out_n) {
    int idx = blockIdx.x * blockDim.x + threadIdx.x;
    float n2 = 0.f;
    if (idx < BB*KK) {
        int b = idx / KK;
        int uid = user[b];
        int slot = g_map[uid];
        int it = item[idx];
        const float4* ue  = reinterpret_cast<const float4*>(user_emb) + (size_t)uid*16;
        const float4* u2  = reinterpret_cast<const float4*>(g_u2) + (size_t)slot*16;
        const float4* ie  = reinterpret_cast<const float4*>(item_emb) + (size_t)it*16;
        const float4* ifw = reinterpret_cast<const float4*>(g_item_featW) + (size_t)it*16;
        float s = 0.f;
        float4 ier[16];
        #pragma unroll
        for (int t = 0; t < 16; t++) {
            float4 a = ue[t], c = ie[t];
            ier[t] = c;
            s  += a.x*c.x + a.y*c.y + a.z*c.z + a.w*c.w;
            n2 += c.x*c.x + c.y*c.y + c.z*c.z + c.w*c.w;
        }
        #pragma unroll
        for (int t = 0; t < 16; t++) {
            float4 a = u2[t], c = ifw[t];
            s  += a.x*c.x + a.y*c.y + a.z*c.z + a.w*c.w;
            n2 += c.x*c.x + c.y*c.y + c.z*c.z + c.w*c.w;
        }
        float s2 = 0.f;
        #pragma unroll
        for (int r = 0; r < RREL; r++) {
            const float4* pr = reinterpret_cast<const float4*>(g_proj) + ((size_t)r*BB + slot)*32;
            const float4* ag = reinterpret_cast<const float4*>(g_item_agg + (size_t)r*IE) + (size_t)it*16;
            float dinv = 1.0f / (g_ig_deg[r*NITEMS + it] + EPSF);
            #pragma unroll
            for (int t = 0; t < 16; t++) {
                float4 a = pr[t], c = ier[t];
                s2 += a.x*c.x + a.y*c.y + a.z*c.z + a.w*c.w;
            }
            #pragma unroll
            for (int t = 0; t < 16; t++) {
                float4 a = pr[16+t], c = ag[t];
                s2 += dinv * (a.x*c.x + a.y*c.y + a.z*c.z + a.w*c.w);
            }
        }
        out[idx] = s + SCORE2_SCALE * s2;
    }
    if (idx < BB) {
        int uid = user[idx];
        int slot = g_map[uid];
        const float4* ue = reinterpret_cast<const float4*>(user_emb) + (size_t)uid*16;
        const float4* u2 = reinterpret_cast<const float4*>(g_u2) + (size_t)slot*16;
        float un = 0.f;
        #pragma unroll
        for (int t = 0; t < 16; t++) {
            float4 a = ue[t]; un += a.x*a.x + a.y*a.y + a.z*a.z + a.w*a.w;
            float4 c = u2[t]; un += c.x*c.x + c.y*c.y + c.z*c.z + c.w*c.w;
        }
        n2 += (float)KK * un;
    }
    __shared__ float red[256];
    red[threadIdx.x] = n2;
    __syncthreads();
    for (int s = 128; s > 0; s >>= 1) {
        if (threadIdx.x < s) red[threadIdx.x] += red[threadIdx.x + s];
        __syncthreads();
    }
    if (threadIdx.x == 0) {
        atomicAdd(&g_l2i, (double)red[0]);
        __threadfence();
        int old = atomicAdd(&g_done, 1);
        if (old == gridDim.x - 1) {
            double total = atomicAdd(&g_l2i, 0.0);
            if (out_n > BB*KK) out[BB*KK] = (float)((double)L2C * total);
        }
    }
}

// ---------------- launch ----------------
extern "C" void kernel_launch(void* const* d_in, const int* in_sizes, int n_in,
                              void* d_out, int out_size) {
    const int*   user       = (const int*)  d_in[0];
    const int*   item       = (const int*)  d_in[1];
    const int*   rel_rows   = (const int*)  d_in[2];
    const int*   rel_cols   = (const int*)  d_in[3];
    const int*   ig_rows    = (const int*)  d_in[4];
    const int*   ig_cols    = (const int*)  d_in[5];
    const float* ig_vals    = (const float*)d_in[6];
    const int*   train_rows = (const int*)  d_in[7];
    const int*   train_cols = (const int*)  d_in[8];
    const float* user_emb   = (const float*)d_in[9];
    const float* item_emb   = (const float*)d_in[10];
    const float* mgnn       = (const float*)d_in[11];
    const float* Wb         = (const float*)d_in[12];
    const float* Wp         = (const float*)d_in[13];
    const float* Wm         = (const float*)d_in[14];
    float* out = (float*)d_out;

    cudaStream_t s2;
    cudaStreamCreateWithFlags(&s2, cudaStreamNonBlocking);
    cudaEvent_t ev_root, ev_zp, ev_map, ev_pre, ev_tr, ev_mm;
    cudaEventCreateWithFlags(&ev_root, cudaEventDisableTiming);
    cudaEventCreateWithFlags(&ev_zp,   cudaEventDisableTiming);
    cudaEventCreateWithFlags(&ev_map,  cudaEventDisableTiming);
    cudaEventCreateWithFlags(&ev_pre,  cudaEventDisableTiming);
    cudaEventCreateWithFlags(&ev_tr,   cudaEventDisableTiming);
    cudaEventCreateWithFlags(&ev_mm,   cudaEventDisableTiming);

    // capture fork anchor
    k_root<<<1, 32>>>();
    cudaEventRecord(ev_root, 0);
    cudaStreamWaitEvent(s2, ev_root, 0);

    // side stream: big-plane zero; event recorded IMMEDIATELY after it
    k_zero_planes<<<(RREL*IE/4 + 255)/256, 256, 0, s2>>>();
    cudaEventRecord(ev_zp, s2);

    // main stream: control zero -> map
    k_zero_ctrl<<<(RREL*BB*128/4 + 255)/256, 256>>>();
    k_map<<<(BB*KK + 255)/256, 256>>>(user, item);
    cudaEventRecord(ev_map, 0);

    // side stream: prescan after map (runs concurrently with scatter_tr)
    cudaStreamWaitEvent(s2, ev_map, 0);
    {
        dim3 grid((NNZ_E/4 + 255)/256, RREL);
        k_prescan_rel<<<grid, 256, 0, s2>>>(rel_rows, rel_cols);
    }
    cudaEventRecord(ev_pre, s2);

    // main: train scatter — needs ONLY zero_planes (ev_zp) + map (stream order)
    cudaStreamWaitEvent(0, ev_zp, 0);
    k_scatter_tr<<<NB_TR, 256>>>(train_rows, train_cols, user_emb);
    cudaEventRecord(ev_tr, 0);

    // side stream: matmul featW (needs item_feat from scatter_tr) overlaps scatter_ig
    cudaStreamWaitEvent(s2, ev_tr, 0);
    k_matmul_featW<<<NB_MM, 256, 0, s2>>>(Wm);
    cudaEventRecord(ev_mm, s2);

    // main: ig scatter — needs nbit from prescan
    cudaStreamWaitEvent(0, ev_pre, 0);
    k_scatter_ig<<<RREL*NB_IG, 256>>>(ig_rows, ig_cols, ig_vals, item_emb);

    {
        dim3 grid(NB_RH, RREL);
        k_rel_heavy<<<grid, 256>>>(item_emb);
    }
    {
        dim3 grid(BB/SLOTS_PB, RREL + 1);
        k_proj<<<grid, 128>>>(Wb, Wp, Wm, mgnn);
    }

    // score needs featW from side stream
    cudaStreamWaitEvent(0, ev_mm, 0);
    k_score<<<NB_SCORE, 256>>>(user, item, user_emb, item_emb, out, out_size);
}